// round 8
// baseline (speedup 1.0000x reference)
#include <cuda_runtime.h>
#include <cuda_bf16.h>
#include <cstdint>
#include <cstddef>

// ---------------------------------------------------------------------------
// Mamba. tf32 mma GEMMs; conv fused into consumers; LN fused into inproj
// (stats kernel + inline normalize); residual fused into outproj epilogue.
// Layouts: res/h (b,s,f) row-major; xt/zt/y (b,d,s); dblt (b,j,s).
// ---------------------------------------------------------------------------

#define NB     4
#define NS     2048
#define DM     256
#define DI     512
#define DSTATE 16
#define NTOK   (NB * NS)

__device__ float g_res [NTOK * DM];
__device__ float g_h   [NTOK * DM];      // final-layer mixer output for head
__device__ float2 g_stats[NTOK];         // per-row {mean, rstd}
__device__ float g_xt  [NB * DI * NS];   // raw conv input, (b,d,s)
__device__ float g_zt  [NB * DI * NS];   // silu(z), (b,d,s)
__device__ float g_dblt[NB * 48 * NS];
__device__ float g_y   [NB * DI * NS];

// ---------------------------------------------------------------------------
__device__ __forceinline__ uint32_t f2tf(float x) {
    uint32_t u;
    asm("cvt.rna.tf32.f32 %0, %1;" : "=r"(u) : "f"(x));
    return u;
}

__device__ __forceinline__ void mma_tf32(float* c, const uint32_t* a,
                                         uint32_t b0, uint32_t b1) {
    asm volatile(
        "mma.sync.aligned.m16n8k8.row.col.f32.tf32.tf32.f32 "
        "{%0,%1,%2,%3},{%4,%5,%6,%7},{%8,%9},{%0,%1,%2,%3};"
        : "+f"(c[0]), "+f"(c[1]), "+f"(c[2]), "+f"(c[3])
        : "r"(a[0]), "r"(a[1]), "r"(a[2]), "r"(a[3]), "r"(b0), "r"(b1));
}

__device__ __forceinline__ uint4 cvt4(float4 v) {
    uint4 u;
    u.x = f2tf(v.x); u.y = f2tf(v.y); u.z = f2tf(v.z); u.w = f2tf(v.w);
    return u;
}

__device__ __forceinline__ float silu_f(float x) {
    return x / (1.f + __expf(-x));
}

__device__ __forceinline__ float softplus_f(float x) {
    return (x > 20.f) ? x : log1pf(__expf(x));
}

// causal 4-tap conv + silu on 4 consecutive outputs given prev/cur float4s
__device__ __forceinline__ float4 conv4(float4 p, float4 c, float4 w, float bias) {
    float4 o;
    o.x = silu_f(bias + w.x * p.y + w.y * p.z + w.z * p.w + w.w * c.x);
    o.y = silu_f(bias + w.x * p.z + w.y * p.w + w.z * c.x + w.w * c.y);
    o.z = silu_f(bias + w.x * p.w + w.y * c.x + w.z * c.y + w.w * c.z);
    o.w = silu_f(bias + w.x * c.x + w.y * c.y + w.z * c.z + w.w * c.w);
    return o;
}

// ---------------------------------------------------------------------------
// embed -> res
// ---------------------------------------------------------------------------
__global__ __launch_bounds__(256)
void embed_kernel(const float* __restrict__ x, const float* __restrict__ W,
                  float* __restrict__ res) {
    __shared__ float xs[15];
    int row = blockIdx.x;
    if (threadIdx.x < 15) xs[threadIdx.x] = x[row * 15 + threadIdx.x];
    __syncthreads();
    int m = threadIdx.x;
    const float* wr = W + m * 15;
    float acc = 0.f;
#pragma unroll
    for (int k = 0; k < 15; k++) acc = fmaf(xs[k], wr[k], acc);
    res[(size_t)row * DM + m] = acc;
}

// ---------------------------------------------------------------------------
// stats: per-row mean/rstd of res
// ---------------------------------------------------------------------------
__global__ __launch_bounds__(256)
void stats_kernel(const float* __restrict__ res, float2* __restrict__ st) {
    int wid = threadIdx.x >> 5, lane = threadIdx.x & 31;
    int row = blockIdx.x * 8 + wid;
    const float* rp = res + (size_t)row * DM;
    float4 v0 = *(const float4*)(rp + lane * 4);
    float4 v1 = *(const float4*)(rp + 128 + lane * 4);
    float s = v0.x + v0.y + v0.z + v0.w + v1.x + v1.y + v1.z + v1.w;
    float q = v0.x*v0.x + v0.y*v0.y + v0.z*v0.z + v0.w*v0.w +
              v1.x*v1.x + v1.y*v1.y + v1.z*v1.z + v1.w*v1.w;
#pragma unroll
    for (int o = 16; o > 0; o >>= 1) {
        s += __shfl_xor_sync(0xffffffffu, s, o);
        q += __shfl_xor_sync(0xffffffffu, q, o);
    }
    if (lane == 0) {
        float m = s * (1.f / 256.f);
        float var = q * (1.f / 256.f) - m * m;
        st[row] = make_float2(m, rsqrtf(var + 1e-5f));
    }
}

// ---------------------------------------------------------------------------
// tc_in (inproj, LN fused on A-load): out = LN(res)(8192,256) * W(1024,256)^T.
// Epilogue writes TRANSPOSED: feat<512 -> xt raw; >=512 -> zt silu'd.
// ---------------------------------------------------------------------------
#define NT_ASZ (128 * 36)
#define NT_BSZ (64 * 36)
#define NT_SMEM ((2 * NT_ASZ + 2 * NT_BSZ) * 4)

__global__ __launch_bounds__(256)
void tc_in(const float* __restrict__ A, const float2* __restrict__ stats,
           const float* __restrict__ nw, const float* __restrict__ nb,
           const float* __restrict__ B,
           float* __restrict__ xt, float* __restrict__ zt) {
    const int K = DM;
    extern __shared__ uint32_t sm_nt[];
    uint32_t* As = sm_nt;
    uint32_t* Bs = sm_nt + 2 * NT_ASZ;
    int tid = threadIdx.x, lane = tid & 31, wid = tid >> 5;
    int m0 = blockIdx.y * 128, n0 = blockIdx.x * 64;
    int wm = (wid >> 1) * 32, wn = (wid & 1) * 32;
    int gr = lane >> 2, gc = lane & 3;
    float acc[2][4][4];
#pragma unroll
    for (int i = 0; i < 2; i++)
#pragma unroll
        for (int j = 0; j < 4; j++)
#pragma unroll
            for (int q = 0; q < 4; q++) acc[i][j][q] = 0.f;
    int la_m = tid >> 3, la_k = (tid & 7) * 4;
    int lb_n = tid >> 2, lb_k = (tid & 3) * 8;
    const float* Apt = A + (size_t)(m0 + la_m) * K + la_k;
    const float* Bpt = B + (size_t)(n0 + lb_n) * K + lb_k;
    float2 stt[4];
#pragma unroll
    for (int i = 0; i < 4; i++) stt[i] = stats[m0 + la_m + i * 32];

    float4 ar[4], br[2], wv, bv;
    wv = *(const float4*)(nw + la_k);
    bv = *(const float4*)(nb + la_k);
#pragma unroll
    for (int i = 0; i < 4; i++) {
        float4 v = *(const float4*)(Apt + (size_t)(i * 32) * K);
        ar[i].x = (v.x - stt[i].x) * stt[i].y * wv.x + bv.x;
        ar[i].y = (v.y - stt[i].x) * stt[i].y * wv.y + bv.y;
        ar[i].z = (v.z - stt[i].x) * stt[i].y * wv.z + bv.z;
        ar[i].w = (v.w - stt[i].x) * stt[i].y * wv.w + bv.w;
    }
    br[0] = *(const float4*)(Bpt);
    br[1] = *(const float4*)(Bpt + 4);
    int buf = 0;
#pragma unroll
    for (int i = 0; i < 4; i++)
        *(uint4*)&As[(la_m + i * 32) * 36 + la_k] = cvt4(ar[i]);
    *(uint4*)&Bs[lb_n * 36 + lb_k]     = cvt4(br[0]);
    *(uint4*)&Bs[lb_n * 36 + lb_k + 4] = cvt4(br[1]);
    __syncthreads();

    for (int k0 = 32; k0 <= K; k0 += 32) {
        if (k0 < K) {
            wv = *(const float4*)(nw + k0 + la_k);
            bv = *(const float4*)(nb + k0 + la_k);
#pragma unroll
            for (int i = 0; i < 4; i++) {
                float4 v = *(const float4*)(Apt + (size_t)(i * 32) * K + k0);
                ar[i].x = (v.x - stt[i].x) * stt[i].y * wv.x + bv.x;
                ar[i].y = (v.y - stt[i].x) * stt[i].y * wv.y + bv.y;
                ar[i].z = (v.z - stt[i].x) * stt[i].y * wv.z + bv.z;
                ar[i].w = (v.w - stt[i].x) * stt[i].y * wv.w + bv.w;
            }
            br[0] = *(const float4*)(Bpt + k0);
            br[1] = *(const float4*)(Bpt + k0 + 4);
        }
        const uint32_t* Ab = As + buf * NT_ASZ;
        const uint32_t* Bb = Bs + buf * NT_BSZ;
#pragma unroll
        for (int ks = 0; ks < 4; ks++) {
            int kb = ks * 8;
            uint32_t a[2][4];
#pragma unroll
            for (int mi = 0; mi < 2; mi++) {
                int rb = wm + mi * 16 + gr;
                a[mi][0] = Ab[rb * 36 + kb + gc];
                a[mi][1] = Ab[(rb + 8) * 36 + kb + gc];
                a[mi][2] = Ab[rb * 36 + kb + gc + 4];
                a[mi][3] = Ab[(rb + 8) * 36 + kb + gc + 4];
            }
#pragma unroll
            for (int ni = 0; ni < 4; ni++) {
                uint32_t b0 = Bb[(wn + ni * 8 + gr) * 36 + kb + gc];
                uint32_t b1 = Bb[(wn + ni * 8 + gr) * 36 + kb + gc + 4];
#pragma unroll
                for (int mi = 0; mi < 2; mi++)
                    mma_tf32(acc[mi][ni], a[mi], b0, b1);
            }
        }
        if (k0 < K) {
            int nb2 = buf ^ 1;
#pragma unroll
            for (int i = 0; i < 4; i++)
                *(uint4*)&As[nb2 * NT_ASZ + (la_m + i * 32) * 36 + la_k] = cvt4(ar[i]);
            *(uint4*)&Bs[nb2 * NT_BSZ + lb_n * 36 + lb_k]     = cvt4(br[0]);
            *(uint4*)&Bs[nb2 * NT_BSZ + lb_n * 36 + lb_k + 4] = cvt4(br[1]);
            __syncthreads();
            buf = nb2;
        }
    }
    // transpose epilogue via smem: st[feat][tok], stride 132
    float* st = (float*)sm_nt;
    __syncthreads();
#pragma unroll
    for (int mi = 0; mi < 2; mi++) {
        int r0 = wm + mi * 16 + gr;
#pragma unroll
        for (int ni = 0; ni < 4; ni++) {
            int cc = wn + ni * 8 + 2 * gc;
            st[cc * 132 + r0]           = acc[mi][ni][0];
            st[(cc + 1) * 132 + r0]     = acc[mi][ni][1];
            st[cc * 132 + r0 + 8]       = acc[mi][ni][2];
            st[(cc + 1) * 132 + r0 + 8] = acc[mi][ni][3];
        }
    }
    __syncthreads();
    int b = m0 / NS, s0 = m0 % NS;
#pragma unroll
    for (int rr = wid; rr < 64; rr += 8) {
        int f = n0 + rr;
        float4 v = *(float4*)&st[rr * 132 + lane * 4];
        if (f < DI) {
            *(float4*)(xt + ((size_t)b * DI + f) * NS + s0 + lane * 4) = v;
        } else {
            v.x = silu_f(v.x); v.y = silu_f(v.y);
            v.z = silu_f(v.z); v.w = silu_f(v.w);
            *(float4*)(zt + ((size_t)b * DI + f - DI) * NS + s0 + lane * 4) = v;
        }
    }
}

// ---------------------------------------------------------------------------
// tc_xp (xproj, conv fused on B-load): dblt(48,s) = xpW(48,512) x conv(xt)(d,s)
// ---------------------------------------------------------------------------
#define XP_ASZ (64 * 36)
#define XP_BSZ (32 * 72)
#define XP_SMEM ((2 * XP_ASZ + 2 * XP_BSZ) * 4)

__global__ __launch_bounds__(256)
void tc_xp(const float* __restrict__ W, const float* __restrict__ X,
           const float* __restrict__ cw, const float* __restrict__ cb,
           float* __restrict__ Dt) {
    extern __shared__ uint32_t sm_xp[];
    uint32_t* As = sm_xp;
    uint32_t* Bs = sm_xp + 2 * XP_ASZ;
    int b = blockIdx.z;
    int s0 = blockIdx.x * 64;
    const float* Xb = X + (size_t)b * DI * NS;
    float* Db = Dt + (size_t)b * 48 * NS;
    int tid = threadIdx.x, lane = tid & 31, wid = tid >> 5;
    int wm = (wid >> 2) * 32, wn = (wid & 3) * 16;
    int gr = lane >> 2, gc = lane & 3;
    float acc[2][2][4];
#pragma unroll
    for (int i = 0; i < 2; i++)
#pragma unroll
        for (int j = 0; j < 2; j++)
#pragma unroll
            for (int q = 0; q < 4; q++) acc[i][j][q] = 0.f;
    int la_m = tid >> 2, la_k = (tid & 3) * 8;
    int bk = tid >> 4, bn4 = (tid & 15) * 4;
    int scol = s0 + bn4;
    bool avalid = (la_m < 48);
    const float* Apt = W + (size_t)la_m * DI + la_k;
    float4 zero = make_float4(0.f, 0.f, 0.f, 0.f);

    float4 ar[2], br[2];
    ar[0] = avalid ? *(const float4*)(Apt)     : zero;
    ar[1] = avalid ? *(const float4*)(Apt + 4) : zero;
#pragma unroll
    for (int i = 0; i < 2; i++) {
        int d = bk + i * 16;
        const float* xr = Xb + (size_t)d * NS;
        float4 p = (scol == 0) ? zero : *(const float4*)(xr + scol - 4);
        float4 c = *(const float4*)(xr + scol);
        br[i] = conv4(p, c, *(const float4*)(cw + d * 4), cb[d]);
    }
    int buf = 0;
    *(uint4*)&As[la_m * 36 + la_k]     = cvt4(ar[0]);
    *(uint4*)&As[la_m * 36 + la_k + 4] = cvt4(ar[1]);
#pragma unroll
    for (int i = 0; i < 2; i++)
        *(uint4*)&Bs[(bk + i * 16) * 72 + bn4] = cvt4(br[i]);
    __syncthreads();

    for (int k0 = 32; k0 <= DI; k0 += 32) {
        if (k0 < DI) {
            ar[0] = avalid ? *(const float4*)(Apt + k0)     : zero;
            ar[1] = avalid ? *(const float4*)(Apt + k0 + 4) : zero;
#pragma unroll
            for (int i = 0; i < 2; i++) {
                int d = k0 + bk + i * 16;
                const float* xr = Xb + (size_t)d * NS;
                float4 p = (scol == 0) ? zero : *(const float4*)(xr + scol - 4);
                float4 c = *(const float4*)(xr + scol);
                br[i] = conv4(p, c, *(const float4*)(cw + d * 4), cb[d]);
            }
        }
        const uint32_t* Ab = As + buf * XP_ASZ;
        const uint32_t* Bb = Bs + buf * XP_BSZ;
#pragma unroll
        for (int ks = 0; ks < 4; ks++) {
            int kb = ks * 8;
            uint32_t a[2][4];
#pragma unroll
            for (int mi = 0; mi < 2; mi++) {
                int rb = wm + mi * 16 + gr;
                a[mi][0] = Ab[rb * 36 + kb + gc];
                a[mi][1] = Ab[(rb + 8) * 36 + kb + gc];
                a[mi][2] = Ab[rb * 36 + kb + gc + 4];
                a[mi][3] = Ab[(rb + 8) * 36 + kb + gc + 4];
            }
#pragma unroll
            for (int ni = 0; ni < 2; ni++) {
                int nn = wn + ni * 8 + gr;
                uint32_t b0 = Bb[(kb + gc) * 72 + nn];
                uint32_t b1 = Bb[(kb + gc + 4) * 72 + nn];
#pragma unroll
                for (int mi = 0; mi < 2; mi++)
                    mma_tf32(acc[mi][ni], a[mi], b0, b1);
            }
        }
        if (k0 < DI) {
            int nb2 = buf ^ 1;
            *(uint4*)&As[nb2 * XP_ASZ + la_m * 36 + la_k]     = cvt4(ar[0]);
            *(uint4*)&As[nb2 * XP_ASZ + la_m * 36 + la_k + 4] = cvt4(ar[1]);
#pragma unroll
            for (int i = 0; i < 2; i++)
                *(uint4*)&Bs[nb2 * XP_BSZ + (bk + i * 16) * 72 + bn4] = cvt4(br[i]);
            __syncthreads();
            buf = nb2;
        }
    }
#pragma unroll
    for (int mi = 0; mi < 2; mi++) {
        int m = wm + mi * 16 + gr;
#pragma unroll
        for (int ni = 0; ni < 2; ni++) {
            int sc = s0 + wn + ni * 8 + 2 * gc;
            if (m < 48)
                *(float2*)(Db + (size_t)m * NS + sc) =
                    make_float2(acc[mi][ni][0], acc[mi][ni][1]);
            if (m + 8 < 48)
                *(float2*)(Db + (size_t)(m + 8) * NS + sc) =
                    make_float2(acc[mi][ni][2], acc[mi][ni][3]);
        }
    }
}

// ---------------------------------------------------------------------------
// scan v3: 256 threads = 16 channels; conv + dtproj fused; chunked staging.
// ---------------------------------------------------------------------------
#define SCH 64

__global__ __launch_bounds__(256)
void scan_kernel(const float* __restrict__ xtp, const float* __restrict__ ztp,
                 const float* __restrict__ dblt,
                 const float* __restrict__ cw, const float* __restrict__ cb,
                 const float* __restrict__ dtW, const float* __restrict__ dtb,
                 const float* __restrict__ Alog, const float* __restrict__ Dp,
                 float* __restrict__ yout) {
    __shared__ float sdp[16][SCH];
    __shared__ float sB [16][SCH + 4];
    __shared__ float sC [16][SCH + 4];
    __shared__ float sdt[16][SCH + 4];
    __shared__ float sx [16][SCH + 4];
    __shared__ float sz [16][SCH + 4];
    __shared__ float sy [16][SCH + 4];
    __shared__ float sW [16][16];
    __shared__ float sbias[16];

    int b = blockIdx.y;
    int d0 = blockIdx.x * 16;
    int tid = threadIdx.x, lane = tid & 31, warp = tid >> 5;
    int dl = lane >> 4, n = lane & 15;
    int dloc = warp * 2 + dl;
    int d = d0 + dloc;

    int rr = tid >> 4, cc = (tid & 15) * 4;   // staging map
    {
        int j = tid & 15;
        sW[rr][j] = dtW[(size_t)(d0 + rr) * 16 + j];
    }
    if (tid < 16) sbias[tid] = dtb[d0 + tid];

    float4 cwv = *(const float4*)(cw + (d0 + rr) * 4);
    float cbv = cb[d0 + rr];
    const float* xrow = xtp + ((size_t)b * DI + d0 + rr) * NS;
    const float* zrow = ztp + ((size_t)b * DI + d0 + rr) * NS;
    float* yrow = yout + ((size_t)b * DI + d0 + rr) * NS;

    float a  = -__expf(Alog[d * DSTATE + n]);
    float Dv = Dp[d];
    float hst = 0.f;
    const float* dpb = dblt + (size_t)b * 48 * NS;
    float4 zero = make_float4(0.f, 0.f, 0.f, 0.f);

    for (int t0 = 0; t0 < NS; t0 += SCH) {
        int t = t0 + cc;
        *(float4*)&sdp[rr][cc] = *(const float4*)(dpb + (size_t)rr * NS + t);
        *(float4*)&sB[rr][cc]  = *(const float4*)(dpb + (size_t)(16 + rr) * NS + t);
        *(float4*)&sC[rr][cc]  = *(const float4*)(dpb + (size_t)(32 + rr) * NS + t);
        {
            float4 p = (t == 0) ? zero : *(const float4*)(xrow + t - 4);
            float4 c = *(const float4*)(xrow + t);
            *(float4*)&sx[rr][cc] = conv4(p, c, cwv, cbv);
            *(float4*)&sz[rr][cc] = *(const float4*)(zrow + t);
        }
        __syncthreads();
        // dt = softplus(W @ dtpre + b)
        {
            float bi = sbias[rr];
            float a0 = bi, a1 = bi, a2 = bi, a3 = bi;
#pragma unroll
            for (int j = 0; j < 16; j++) {
                float w = sW[rr][j];
                a0 = fmaf(w, sdp[j][cc],     a0);
                a1 = fmaf(w, sdp[j][cc + 1], a1);
                a2 = fmaf(w, sdp[j][cc + 2], a2);
                a3 = fmaf(w, sdp[j][cc + 3], a3);
            }
            sdt[rr][cc]     = softplus_f(a0);
            sdt[rr][cc + 1] = softplus_f(a1);
            sdt[rr][cc + 2] = softplus_f(a2);
            sdt[rr][cc + 3] = softplus_f(a3);
        }
        __syncthreads();
        // recurrence
        for (int g = 0; g < SCH; g += 4) {
            float4 dt4 = *(const float4*)&sdt[dloc][g];
            float4 x4  = *(const float4*)&sx[dloc][g];
            float4 z4  = *(const float4*)&sz[dloc][g];
            float4 B4  = *(const float4*)&sB[n][g];
            float4 C4  = *(const float4*)&sC[n][g];
            float yo[4];
#pragma unroll
            for (int j = 0; j < 4; j++) {
                float dtv = (&dt4.x)[j], xv = (&x4.x)[j], zv = (&z4.x)[j];
                float Bv = (&B4.x)[j], Cv = (&C4.x)[j];
                float dA = __expf(dtv * a);
                hst = fmaf(dA, hst, dtv * xv * Bv);
                float p = hst * Cv;
                p += __shfl_xor_sync(0xffffffffu, p, 1);
                p += __shfl_xor_sync(0xffffffffu, p, 2);
                p += __shfl_xor_sync(0xffffffffu, p, 4);
                p += __shfl_xor_sync(0xffffffffu, p, 8);
                yo[j] = fmaf(Dv, xv, p) * zv;
            }
            if (n == 0)
                *(float4*)&sy[dloc][g] = make_float4(yo[0], yo[1], yo[2], yo[3]);
        }
        __syncthreads();
        *(float4*)(yrow + t) = *(float4*)&sy[rr][cc];
        __syncthreads();
    }
}

// ---------------------------------------------------------------------------
// tc_op (outproj + residual): res(b,s,dm) += W(256,512) x y(d,s).
// Writes h only when last layer (for head).
// ---------------------------------------------------------------------------
#define OP_ASZ (128 * 36)
#define OP_BSZ (32 * 72)
#define OP_SMEM ((2 * OP_ASZ + 2 * OP_BSZ) * 4)

__global__ __launch_bounds__(256)
void tc_op(const float* __restrict__ W, const float* __restrict__ Y,
           float* __restrict__ RES, float* __restrict__ H, int write_h) {
    extern __shared__ uint32_t sm_op[];
    uint32_t* As = sm_op;
    uint32_t* Bs = sm_op + 2 * OP_ASZ;
    int b = blockIdx.z;
    int m0 = blockIdx.y * 128, s0 = blockIdx.x * 64;
    const float* Yb = Y + (size_t)b * DI * NS;
    int tid = threadIdx.x, lane = tid & 31, wid = tid >> 5;
    int wm = (wid >> 1) * 32, wn = (wid & 1) * 32;
    int gr = lane >> 2, gc = lane & 3;
    float acc[2][4][4];
#pragma unroll
    for (int i = 0; i < 2; i++)
#pragma unroll
        for (int j = 0; j < 4; j++)
#pragma unroll
            for (int q = 0; q < 4; q++) acc[i][j][q] = 0.f;
    int la_m = tid >> 3, la_k = (tid & 7) * 4;
    int bk = tid >> 4, bn4 = (tid & 15) * 4;
    const float* Apt = W + (size_t)(m0 + la_m) * DI + la_k;
    float4 ar[4], br[2];
#pragma unroll
    for (int i = 0; i < 4; i++) ar[i] = *(const float4*)(Apt + (size_t)(i * 32) * DI);
#pragma unroll
    for (int i = 0; i < 2; i++)
        br[i] = *(const float4*)(Yb + (size_t)(bk + i * 16) * NS + s0 + bn4);
    int buf = 0;
#pragma unroll
    for (int i = 0; i < 4; i++)
        *(uint4*)&As[(la_m + i * 32) * 36 + la_k] = cvt4(ar[i]);
#pragma unroll
    for (int i = 0; i < 2; i++)
        *(uint4*)&Bs[(bk + i * 16) * 72 + bn4] = cvt4(br[i]);
    __syncthreads();

    for (int k0 = 32; k0 <= DI; k0 += 32) {
        if (k0 < DI) {
#pragma unroll
            for (int i = 0; i < 4; i++)
                ar[i] = *(const float4*)(Apt + (size_t)(i * 32) * DI + k0);
#pragma unroll
            for (int i = 0; i < 2; i++)
                br[i] = *(const float4*)(Yb + (size_t)(k0 + bk + i * 16) * NS + s0 + bn4);
        }
        const uint32_t* Ab = As + buf * OP_ASZ;
        const uint32_t* Bb = Bs + buf * OP_BSZ;
#pragma unroll
        for (int ks = 0; ks < 4; ks++) {
            int kb = ks * 8;
            uint32_t a[2][4];
#pragma unroll
            for (int mi = 0; mi < 2; mi++) {
                int rb = wm + mi * 16 + gr;
                a[mi][0] = Ab[rb * 36 + kb + gc];
                a[mi][1] = Ab[(rb + 8) * 36 + kb + gc];
                a[mi][2] = Ab[rb * 36 + kb + gc + 4];
                a[mi][3] = Ab[(rb + 8) * 36 + kb + gc + 4];
            }
#pragma unroll
            for (int ni = 0; ni < 4; ni++) {
                int nn = wn + ni * 8 + gr;
                uint32_t b0 = Bb[(kb + gc) * 72 + nn];
                uint32_t b1 = Bb[(kb + gc + 4) * 72 + nn];
#pragma unroll
                for (int mi = 0; mi < 2; mi++)
                    mma_tf32(acc[mi][ni], a[mi], b0, b1);
            }
        }
        if (k0 < DI) {
            int nb2 = buf ^ 1;
#pragma unroll
            for (int i = 0; i < 4; i++)
                *(uint4*)&As[nb2 * OP_ASZ + (la_m + i * 32) * 36 + la_k] = cvt4(ar[i]);
#pragma unroll
            for (int i = 0; i < 2; i++)
                *(uint4*)&Bs[nb2 * OP_BSZ + (bk + i * 16) * 72 + bn4] = cvt4(br[i]);
            __syncthreads();
            buf = nb2;
        }
    }
#pragma unroll
    for (int mi = 0; mi < 2; mi++) {
        int dm = m0 + wm + mi * 16 + gr;
#pragma unroll
        for (int ni = 0; ni < 4; ni++) {
            int s = s0 + wn + ni * 8 + 2 * gc;
            size_t r0 = (size_t)(b * NS + s) * DM;
            size_t r1 = (size_t)(b * NS + s + 1) * DM;
            RES[r0 + dm]     += acc[mi][ni][0];
            RES[r1 + dm]     += acc[mi][ni][1];
            RES[r0 + dm + 8] += acc[mi][ni][2];
            RES[r1 + dm + 8] += acc[mi][ni][3];
            if (write_h) {
                H[r0 + dm]     = acc[mi][ni][0];
                H[r1 + dm]     = acc[mi][ni][1];
                H[r0 + dm + 8] = acc[mi][ni][2];
                H[r1 + dm + 8] = acc[mi][ni][3];
            }
        }
    }
}

// ---------------------------------------------------------------------------
// head: out[row] = dot(h[row,:], out_W)
// ---------------------------------------------------------------------------
__global__ __launch_bounds__(256)
void head_kernel(const float* __restrict__ hin, const float* __restrict__ w,
                 float* __restrict__ out) {
    int wid = threadIdx.x >> 5, lane = threadIdx.x & 31;
    int row = blockIdx.x * 8 + wid;
    const float* hp = hin + (size_t)row * DM;
    int c0 = lane * 4, c1 = 128 + lane * 4;
    float4 v0 = *(const float4*)(hp + c0);
    float4 v1 = *(const float4*)(hp + c1);
    float4 w0 = *(const float4*)(w + c0);
    float4 w1 = *(const float4*)(w + c1);
    float s = v0.x*w0.x + v0.y*w0.y + v0.z*w0.z + v0.w*w0.w +
              v1.x*w1.x + v1.y*w1.y + v1.z*w1.z + v1.w*w1.w;
#pragma unroll
    for (int o = 16; o > 0; o >>= 1) s += __shfl_xor_sync(0xffffffffu, s, o);
    if (lane == 0) out[row] = s;
}

// ---------------------------------------------------------------------------
// host
// ---------------------------------------------------------------------------
extern "C" void kernel_launch(void* const* d_in, const int* in_sizes, int n_in,
                              void* d_out, int out_size) {
    const float* x_src     = (const float*)d_in[0];
    const float* in_W      = (const float*)d_in[2];
    const float* norm_w    = (const float*)d_in[3];
    const float* norm_b    = (const float*)d_in[4];
    const float* inproj_W  = (const float*)d_in[5];
    const float* conv_w    = (const float*)d_in[6];
    const float* conv_b    = (const float*)d_in[7];
    const float* xproj_W   = (const float*)d_in[8];
    const float* dtproj_W  = (const float*)d_in[9];
    const float* dtproj_b  = (const float*)d_in[10];
    const float* A_log     = (const float*)d_in[11];
    const float* D_param   = (const float*)d_in[12];
    const float* outproj_W = (const float*)d_in[13];
    const float* out_W     = (const float*)d_in[14];
    float* out = (float*)d_out;

    static int smem_set = 0;
    if (!smem_set) {
        cudaFuncSetAttribute(tc_in, cudaFuncAttributeMaxDynamicSharedMemorySize,
                             NT_SMEM);
        cudaFuncSetAttribute(tc_op, cudaFuncAttributeMaxDynamicSharedMemorySize,
                             OP_SMEM);
        cudaFuncSetAttribute(tc_xp, cudaFuncAttributeMaxDynamicSharedMemorySize,
                             XP_SMEM);
        smem_set = 1;
    }

    float *pres, *ph, *pxt, *pzt, *pdblt, *py;
    float2* pstats;
    cudaGetSymbolAddress((void**)&pres,  g_res);
    cudaGetSymbolAddress((void**)&ph,    g_h);
    cudaGetSymbolAddress((void**)&pstats, g_stats);
    cudaGetSymbolAddress((void**)&pxt,   g_xt);
    cudaGetSymbolAddress((void**)&pzt,   g_zt);
    cudaGetSymbolAddress((void**)&pdblt, g_dblt);
    cudaGetSymbolAddress((void**)&py,    g_y);

    embed_kernel<<<NTOK, 256>>>(x_src, in_W, pres);

    for (int l = 0; l < 4; l++) {
        stats_kernel<<<NTOK / 8, 256>>>(pres, pstats);
        tc_in<<<dim3(1024 / 64, NTOK / 128), 256, NT_SMEM>>>(
            pres, pstats, norm_w + l * DM, norm_b + l * DM,
            inproj_W + (size_t)l * 1024 * DM, pxt, pzt);
        tc_xp<<<dim3(NS / 64, 1, NB), 256, XP_SMEM>>>(
            xproj_W + (size_t)l * 48 * DI, pxt,
            conv_w + (size_t)l * DI * 4, conv_b + (size_t)l * DI, pdblt);
        scan_kernel<<<dim3(DI / 16, NB), 256>>>(
            pxt, pzt, pdblt,
            conv_w + (size_t)l * DI * 4, conv_b + (size_t)l * DI,
            dtproj_W + (size_t)l * DI * 16, dtproj_b + (size_t)l * DI,
            A_log + (size_t)l * DI * DSTATE, D_param + (size_t)l * DI, py);
        tc_op<<<dim3(NS / 64, DM / 128, NB), 256, OP_SMEM>>>(
            outproj_W + (size_t)l * DM * DI, py, pres, ph, (l == 3) ? 1 : 0);
    }

    head_kernel<<<NTOK / 8, 256>>>(ph, out_W, out);
}

// round 9
// speedup vs baseline: 1.0924x; 1.0924x over previous
#include <cuda_runtime.h>
#include <cuda_bf16.h>
#include <cstdint>
#include <cstddef>

// ---------------------------------------------------------------------------
// Mamba. tf32 mma GEMMs (double-buffered); LN fused into inproj via stats;
// residual fused into outproj; standalone streaming conv; scan with fused
// dtproj + smem chunk staging.
// Layouts: res/h (b,s,f) row-major; xt/zt/xc/y (b,d,s); dblt (b,j,s).
// ---------------------------------------------------------------------------

#define NB     4
#define NS     2048
#define DM     256
#define DI     512
#define DSTATE 16
#define NTOK   (NB * NS)

__device__ float g_res [NTOK * DM];
__device__ float g_h   [NTOK * DM];
__device__ float2 g_stats[NTOK];
__device__ float g_xt  [NB * DI * NS];
__device__ float g_zt  [NB * DI * NS];
__device__ float g_xc  [NB * DI * NS];
__device__ float g_dblt[NB * 48 * NS];
__device__ float g_y   [NB * DI * NS];

// ---------------------------------------------------------------------------
__device__ __forceinline__ uint32_t f2tf(float x) {
    uint32_t u;
    asm("cvt.rna.tf32.f32 %0, %1;" : "=r"(u) : "f"(x));
    return u;
}

__device__ __forceinline__ void mma_tf32(float* c, const uint32_t* a,
                                         uint32_t b0, uint32_t b1) {
    asm volatile(
        "mma.sync.aligned.m16n8k8.row.col.f32.tf32.tf32.f32 "
        "{%0,%1,%2,%3},{%4,%5,%6,%7},{%8,%9},{%0,%1,%2,%3};"
        : "+f"(c[0]), "+f"(c[1]), "+f"(c[2]), "+f"(c[3])
        : "r"(a[0]), "r"(a[1]), "r"(a[2]), "r"(a[3]), "r"(b0), "r"(b1));
}

__device__ __forceinline__ uint4 cvt4(float4 v) {
    uint4 u;
    u.x = f2tf(v.x); u.y = f2tf(v.y); u.z = f2tf(v.z); u.w = f2tf(v.w);
    return u;
}

__device__ __forceinline__ float silu_f(float x) {
    return x / (1.f + __expf(-x));
}

__device__ __forceinline__ float softplus_f(float x) {
    return (x > 20.f) ? x : log1pf(__expf(x));
}

// ---------------------------------------------------------------------------
// embed -> res
// ---------------------------------------------------------------------------
__global__ __launch_bounds__(256)
void embed_kernel(const float* __restrict__ x, const float* __restrict__ W,
                  float* __restrict__ res) {
    __shared__ float xs[15];
    int row = blockIdx.x;
    if (threadIdx.x < 15) xs[threadIdx.x] = x[row * 15 + threadIdx.x];
    __syncthreads();
    int m = threadIdx.x;
    const float* wr = W + m * 15;
    float acc = 0.f;
#pragma unroll
    for (int k = 0; k < 15; k++) acc = fmaf(xs[k], wr[k], acc);
    res[(size_t)row * DM + m] = acc;
}

// ---------------------------------------------------------------------------
// stats: per-row mean/rstd of res
// ---------------------------------------------------------------------------
__global__ __launch_bounds__(256)
void stats_kernel(const float* __restrict__ res, float2* __restrict__ st) {
    int wid = threadIdx.x >> 5, lane = threadIdx.x & 31;
    int row = blockIdx.x * 8 + wid;
    const float* rp = res + (size_t)row * DM;
    float4 v0 = *(const float4*)(rp + lane * 4);
    float4 v1 = *(const float4*)(rp + 128 + lane * 4);
    float s = v0.x + v0.y + v0.z + v0.w + v1.x + v1.y + v1.z + v1.w;
    float q = v0.x*v0.x + v0.y*v0.y + v0.z*v0.z + v0.w*v0.w +
              v1.x*v1.x + v1.y*v1.y + v1.z*v1.z + v1.w*v1.w;
#pragma unroll
    for (int o = 16; o > 0; o >>= 1) {
        s += __shfl_xor_sync(0xffffffffu, s, o);
        q += __shfl_xor_sync(0xffffffffu, q, o);
    }
    if (lane == 0) {
        float m = s * (1.f / 256.f);
        float var = q * (1.f / 256.f) - m * m;
        st[row] = make_float2(m, rsqrtf(var + 1e-5f));
    }
}

// ---------------------------------------------------------------------------
// tc_in (inproj, LN fused on A-load): out = LN(res)(8192,256) * W(1024,256)^T.
// Epilogue writes TRANSPOSED: feat<512 -> xt raw; >=512 -> zt silu'd.
// ---------------------------------------------------------------------------
#define NT_ASZ (128 * 36)
#define NT_BSZ (64 * 36)
#define NT_SMEM ((2 * NT_ASZ + 2 * NT_BSZ) * 4)

__global__ __launch_bounds__(256)
void tc_in(const float* __restrict__ A, const float2* __restrict__ stats,
           const float* __restrict__ nw, const float* __restrict__ nb,
           const float* __restrict__ B,
           float* __restrict__ xt, float* __restrict__ zt) {
    const int K = DM;
    extern __shared__ uint32_t sm_nt[];
    uint32_t* As = sm_nt;
    uint32_t* Bs = sm_nt + 2 * NT_ASZ;
    int tid = threadIdx.x, lane = tid & 31, wid = tid >> 5;
    int m0 = blockIdx.y * 128, n0 = blockIdx.x * 64;
    int wm = (wid >> 1) * 32, wn = (wid & 1) * 32;
    int gr = lane >> 2, gc = lane & 3;
    float acc[2][4][4];
#pragma unroll
    for (int i = 0; i < 2; i++)
#pragma unroll
        for (int j = 0; j < 4; j++)
#pragma unroll
            for (int q = 0; q < 4; q++) acc[i][j][q] = 0.f;
    int la_m = tid >> 3, la_k = (tid & 7) * 4;
    int lb_n = tid >> 2, lb_k = (tid & 3) * 8;
    const float* Apt = A + (size_t)(m0 + la_m) * K + la_k;
    const float* Bpt = B + (size_t)(n0 + lb_n) * K + lb_k;
    float2 stt[4];
#pragma unroll
    for (int i = 0; i < 4; i++) stt[i] = stats[m0 + la_m + i * 32];

    float4 ar[4], br[2], wv, bv;
    wv = *(const float4*)(nw + la_k);
    bv = *(const float4*)(nb + la_k);
#pragma unroll
    for (int i = 0; i < 4; i++) {
        float4 v = *(const float4*)(Apt + (size_t)(i * 32) * K);
        ar[i].x = (v.x - stt[i].x) * stt[i].y * wv.x + bv.x;
        ar[i].y = (v.y - stt[i].x) * stt[i].y * wv.y + bv.y;
        ar[i].z = (v.z - stt[i].x) * stt[i].y * wv.z + bv.z;
        ar[i].w = (v.w - stt[i].x) * stt[i].y * wv.w + bv.w;
    }
    br[0] = *(const float4*)(Bpt);
    br[1] = *(const float4*)(Bpt + 4);
    int buf = 0;
#pragma unroll
    for (int i = 0; i < 4; i++)
        *(uint4*)&As[(la_m + i * 32) * 36 + la_k] = cvt4(ar[i]);
    *(uint4*)&Bs[lb_n * 36 + lb_k]     = cvt4(br[0]);
    *(uint4*)&Bs[lb_n * 36 + lb_k + 4] = cvt4(br[1]);
    __syncthreads();

    for (int k0 = 32; k0 <= K; k0 += 32) {
        if (k0 < K) {
            wv = *(const float4*)(nw + k0 + la_k);
            bv = *(const float4*)(nb + k0 + la_k);
#pragma unroll
            for (int i = 0; i < 4; i++) {
                float4 v = *(const float4*)(Apt + (size_t)(i * 32) * K + k0);
                ar[i].x = (v.x - stt[i].x) * stt[i].y * wv.x + bv.x;
                ar[i].y = (v.y - stt[i].x) * stt[i].y * wv.y + bv.y;
                ar[i].z = (v.z - stt[i].x) * stt[i].y * wv.z + bv.z;
                ar[i].w = (v.w - stt[i].x) * stt[i].y * wv.w + bv.w;
            }
            br[0] = *(const float4*)(Bpt + k0);
            br[1] = *(const float4*)(Bpt + k0 + 4);
        }
        const uint32_t* Ab = As + buf * NT_ASZ;
        const uint32_t* Bb = Bs + buf * NT_BSZ;
#pragma unroll
        for (int ks = 0; ks < 4; ks++) {
            int kb = ks * 8;
            uint32_t a[2][4];
#pragma unroll
            for (int mi = 0; mi < 2; mi++) {
                int rb = wm + mi * 16 + gr;
                a[mi][0] = Ab[rb * 36 + kb + gc];
                a[mi][1] = Ab[(rb + 8) * 36 + kb + gc];
                a[mi][2] = Ab[rb * 36 + kb + gc + 4];
                a[mi][3] = Ab[(rb + 8) * 36 + kb + gc + 4];
            }
#pragma unroll
            for (int ni = 0; ni < 4; ni++) {
                uint32_t b0 = Bb[(wn + ni * 8 + gr) * 36 + kb + gc];
                uint32_t b1 = Bb[(wn + ni * 8 + gr) * 36 + kb + gc + 4];
#pragma unroll
                for (int mi = 0; mi < 2; mi++)
                    mma_tf32(acc[mi][ni], a[mi], b0, b1);
            }
        }
        if (k0 < K) {
            int nb2 = buf ^ 1;
#pragma unroll
            for (int i = 0; i < 4; i++)
                *(uint4*)&As[nb2 * NT_ASZ + (la_m + i * 32) * 36 + la_k] = cvt4(ar[i]);
            *(uint4*)&Bs[nb2 * NT_BSZ + lb_n * 36 + lb_k]     = cvt4(br[0]);
            *(uint4*)&Bs[nb2 * NT_BSZ + lb_n * 36 + lb_k + 4] = cvt4(br[1]);
            __syncthreads();
            buf = nb2;
        }
    }
    // transpose epilogue via smem: st[feat][tok], stride 132
    float* st = (float*)sm_nt;
    __syncthreads();
#pragma unroll
    for (int mi = 0; mi < 2; mi++) {
        int r0 = wm + mi * 16 + gr;
#pragma unroll
        for (int ni = 0; ni < 4; ni++) {
            int cc = wn + ni * 8 + 2 * gc;
            st[cc * 132 + r0]           = acc[mi][ni][0];
            st[(cc + 1) * 132 + r0]     = acc[mi][ni][1];
            st[cc * 132 + r0 + 8]       = acc[mi][ni][2];
            st[(cc + 1) * 132 + r0 + 8] = acc[mi][ni][3];
        }
    }
    __syncthreads();
    int b = m0 / NS, s0 = m0 % NS;
#pragma unroll
    for (int rr = wid; rr < 64; rr += 8) {
        int f = n0 + rr;
        float4 v = *(float4*)&st[rr * 132 + lane * 4];
        if (f < DI) {
            *(float4*)(xt + ((size_t)b * DI + f) * NS + s0 + lane * 4) = v;
        } else {
            v.x = silu_f(v.x); v.y = silu_f(v.y);
            v.z = silu_f(v.z); v.w = silu_f(v.w);
            *(float4*)(zt + ((size_t)b * DI + f - DI) * NS + s0 + lane * 4) = v;
        }
    }
}

// ---------------------------------------------------------------------------
// conv_t: causal 4-tap depthwise conv + SiLU on (b,d,s) layout, streaming.
// ---------------------------------------------------------------------------
__global__ __launch_bounds__(256)
void conv_t(const float* __restrict__ xt, const float* __restrict__ cw,
            const float* __restrict__ cb, float* __restrict__ xc) {
    int d = blockIdx.x, b = blockIdx.y;
    const float* row = xt + ((size_t)b * DI + d) * NS;
    float* orow = xc + ((size_t)b * DI + d) * NS;
    float w0 = cw[d * 4 + 0], w1 = cw[d * 4 + 1];
    float w2 = cw[d * 4 + 2], w3 = cw[d * 4 + 3];
    float bias = cb[d];
    int s = threadIdx.x * 8;
    float in[12];
    float4 A = (s == 0) ? make_float4(0.f, 0.f, 0.f, 0.f)
                        : *(const float4*)(row + s - 4);
    float4 Bv = *(const float4*)(row + s);
    float4 Cv = *(const float4*)(row + s + 4);
    in[0] = A.x; in[1] = A.y; in[2] = A.z; in[3] = A.w;
    in[4] = Bv.x; in[5] = Bv.y; in[6] = Bv.z; in[7] = Bv.w;
    in[8] = Cv.x; in[9] = Cv.y; in[10] = Cv.z; in[11] = Cv.w;
    float o[8];
#pragma unroll
    for (int k = 0; k < 8; k++) {
        float a = bias + w0 * in[k + 1] + w1 * in[k + 2]
                       + w2 * in[k + 3] + w3 * in[k + 4];
        o[k] = silu_f(a);
    }
    *(float4*)(orow + s)     = make_float4(o[0], o[1], o[2], o[3]);
    *(float4*)(orow + s + 4) = make_float4(o[4], o[5], o[6], o[7]);
}

// ---------------------------------------------------------------------------
// tc_xp (xproj): per batch, dblt(48, s) = xpW(48,512) x xc(d,s); K=512.
// ---------------------------------------------------------------------------
#define XP_ASZ (64 * 36)
#define XP_BSZ (32 * 72)
#define XP_SMEM ((2 * XP_ASZ + 2 * XP_BSZ) * 4)

__global__ __launch_bounds__(256)
void tc_xp(const float* __restrict__ W, const float* __restrict__ X,
           float* __restrict__ Dt) {
    extern __shared__ uint32_t sm_xp[];
    uint32_t* As = sm_xp;
    uint32_t* Bs = sm_xp + 2 * XP_ASZ;
    int b = blockIdx.z;
    int s0 = blockIdx.x * 64;
    const float* Xb = X + (size_t)b * DI * NS;
    float* Db = Dt + (size_t)b * 48 * NS;
    int tid = threadIdx.x, lane = tid & 31, wid = tid >> 5;
    int wm = (wid >> 2) * 32, wn = (wid & 3) * 16;
    int gr = lane >> 2, gc = lane & 3;
    float acc[2][2][4];
#pragma unroll
    for (int i = 0; i < 2; i++)
#pragma unroll
        for (int j = 0; j < 2; j++)
#pragma unroll
            for (int q = 0; q < 4; q++) acc[i][j][q] = 0.f;
    int la_m = tid >> 2, la_k = (tid & 3) * 8;
    int bk = tid >> 4, bn4 = (tid & 15) * 4;
    bool avalid = (la_m < 48);
    const float* Apt = W + (size_t)la_m * DI + la_k;
    float4 ar[2], br[2];
    float4 zero = make_float4(0.f, 0.f, 0.f, 0.f);
    ar[0] = avalid ? *(const float4*)(Apt)     : zero;
    ar[1] = avalid ? *(const float4*)(Apt + 4) : zero;
#pragma unroll
    for (int i = 0; i < 2; i++)
        br[i] = *(const float4*)(Xb + (size_t)(bk + i * 16) * NS + s0 + bn4);
    int buf = 0;
    *(uint4*)&As[la_m * 36 + la_k]     = cvt4(ar[0]);
    *(uint4*)&As[la_m * 36 + la_k + 4] = cvt4(ar[1]);
#pragma unroll
    for (int i = 0; i < 2; i++)
        *(uint4*)&Bs[(bk + i * 16) * 72 + bn4] = cvt4(br[i]);
    __syncthreads();

    for (int k0 = 32; k0 <= DI; k0 += 32) {
        if (k0 < DI) {
            ar[0] = avalid ? *(const float4*)(Apt + k0)     : zero;
            ar[1] = avalid ? *(const float4*)(Apt + k0 + 4) : zero;
#pragma unroll
            for (int i = 0; i < 2; i++)
                br[i] = *(const float4*)(Xb + (size_t)(k0 + bk + i * 16) * NS + s0 + bn4);
        }
        const uint32_t* Ab = As + buf * XP_ASZ;
        const uint32_t* Bb = Bs + buf * XP_BSZ;
#pragma unroll
        for (int ks = 0; ks < 4; ks++) {
            int kb = ks * 8;
            uint32_t a[2][4];
#pragma unroll
            for (int mi = 0; mi < 2; mi++) {
                int rb = wm + mi * 16 + gr;
                a[mi][0] = Ab[rb * 36 + kb + gc];
                a[mi][1] = Ab[(rb + 8) * 36 + kb + gc];
                a[mi][2] = Ab[rb * 36 + kb + gc + 4];
                a[mi][3] = Ab[(rb + 8) * 36 + kb + gc + 4];
            }
#pragma unroll
            for (int ni = 0; ni < 2; ni++) {
                int nn = wn + ni * 8 + gr;
                uint32_t b0 = Bb[(kb + gc) * 72 + nn];
                uint32_t b1 = Bb[(kb + gc + 4) * 72 + nn];
#pragma unroll
                for (int mi = 0; mi < 2; mi++)
                    mma_tf32(acc[mi][ni], a[mi], b0, b1);
            }
        }
        if (k0 < DI) {
            int nb2 = buf ^ 1;
            *(uint4*)&As[nb2 * XP_ASZ + la_m * 36 + la_k]     = cvt4(ar[0]);
            *(uint4*)&As[nb2 * XP_ASZ + la_m * 36 + la_k + 4] = cvt4(ar[1]);
#pragma unroll
            for (int i = 0; i < 2; i++)
                *(uint4*)&Bs[nb2 * XP_BSZ + (bk + i * 16) * 72 + bn4] = cvt4(br[i]);
            __syncthreads();
            buf = nb2;
        }
    }
#pragma unroll
    for (int mi = 0; mi < 2; mi++) {
        int m = wm + mi * 16 + gr;
#pragma unroll
        for (int ni = 0; ni < 2; ni++) {
            int sc = s0 + wn + ni * 8 + 2 * gc;
            if (m < 48)
                *(float2*)(Db + (size_t)m * NS + sc) =
                    make_float2(acc[mi][ni][0], acc[mi][ni][1]);
            if (m + 8 < 48)
                *(float2*)(Db + (size_t)(m + 8) * NS + sc) =
                    make_float2(acc[mi][ni][2], acc[mi][ni][3]);
        }
    }
}

// ---------------------------------------------------------------------------
// scan v2: fused dtproj + chunked smem staging. 128 threads = 8 channels.
// ---------------------------------------------------------------------------
#define SCH 64

__global__ __launch_bounds__(128)
void scan_kernel(const float* __restrict__ xcp, const float* __restrict__ ztp,
                 const float* __restrict__ dblt,
                 const float* __restrict__ dtW, const float* __restrict__ dtb,
                 const float* __restrict__ Alog, const float* __restrict__ Dp,
                 float* __restrict__ yout) {
    __shared__ float sdp[16][SCH];
    __shared__ float sB [16][SCH + 4];
    __shared__ float sC [16][SCH + 4];
    __shared__ float sdt[8][SCH + 4];
    __shared__ float sx [8][SCH + 4];
    __shared__ float sz [8][SCH + 4];
    __shared__ float sy [8][SCH + 4];
    __shared__ float sW [8][16];
    __shared__ float sbias[8];

    int b = blockIdx.y;
    int d0 = blockIdx.x * 8;
    int tid = threadIdx.x, lane = tid & 31, warp = tid >> 5;
    int dl = lane >> 4, n = lane & 15;
    int dloc = warp * 2 + dl;
    int d = d0 + dloc;

    {
        int dd = tid >> 4, j = tid & 15;
        sW[dd][j] = dtW[(size_t)(d0 + dd) * 16 + j];
    }
    if (tid < 8) sbias[tid] = dtb[d0 + tid];

    float a  = -__expf(Alog[d * DSTATE + n]);
    float Dv = Dp[d];
    float hst = 0.f;
    const float* dpb = dblt + (size_t)b * 48 * NS;

    for (int t0 = 0; t0 < NS; t0 += SCH) {
        {
            int r = tid >> 3, c = (tid & 7) * 8;
            *(float4*)&sdp[r][c]     = *(const float4*)(dpb + (size_t)r * NS + t0 + c);
            *(float4*)&sdp[r][c + 4] = *(const float4*)(dpb + (size_t)r * NS + t0 + c + 4);
            *(float4*)&sB[r][c]      = *(const float4*)(dpb + (size_t)(16 + r) * NS + t0 + c);
            *(float4*)&sB[r][c + 4]  = *(const float4*)(dpb + (size_t)(16 + r) * NS + t0 + c + 4);
            *(float4*)&sC[r][c]      = *(const float4*)(dpb + (size_t)(32 + r) * NS + t0 + c);
            *(float4*)&sC[r][c + 4]  = *(const float4*)(dpb + (size_t)(32 + r) * NS + t0 + c + 4);
        }
        {
            int r = tid >> 4, c = (tid & 15) * 4;
            *(float4*)&sx[r][c] = *(const float4*)(xcp + ((size_t)b * DI + d0 + r) * NS + t0 + c);
            *(float4*)&sz[r][c] = *(const float4*)(ztp + ((size_t)b * DI + d0 + r) * NS + t0 + c);
        }
        __syncthreads();
        {
            int dd = tid >> 4, tt = (tid & 15) * 4;
            float bi = sbias[dd];
            float a0 = bi, a1 = bi, a2 = bi, a3 = bi;
#pragma unroll
            for (int j = 0; j < 16; j++) {
                float w = sW[dd][j];
                a0 = fmaf(w, sdp[j][tt],     a0);
                a1 = fmaf(w, sdp[j][tt + 1], a1);
                a2 = fmaf(w, sdp[j][tt + 2], a2);
                a3 = fmaf(w, sdp[j][tt + 3], a3);
            }
            sdt[dd][tt]     = softplus_f(a0);
            sdt[dd][tt + 1] = softplus_f(a1);
            sdt[dd][tt + 2] = softplus_f(a2);
            sdt[dd][tt + 3] = softplus_f(a3);
        }
        __syncthreads();
        for (int g = 0; g < SCH; g += 4) {
            float4 dt4 = *(const float4*)&sdt[dloc][g];
            float4 x4  = *(const float4*)&sx[dloc][g];
            float4 z4  = *(const float4*)&sz[dloc][g];
            float4 B4  = *(const float4*)&sB[n][g];
            float4 C4  = *(const float4*)&sC[n][g];
            float yo[4];
#pragma unroll
            for (int j = 0; j < 4; j++) {
                float dtv = (&dt4.x)[j], xv = (&x4.x)[j], zv = (&z4.x)[j];
                float Bv = (&B4.x)[j], Cv = (&C4.x)[j];
                float dA = __expf(dtv * a);
                hst = fmaf(dA, hst, dtv * xv * Bv);
                float p = hst * Cv;
                p += __shfl_xor_sync(0xffffffffu, p, 1);
                p += __shfl_xor_sync(0xffffffffu, p, 2);
                p += __shfl_xor_sync(0xffffffffu, p, 4);
                p += __shfl_xor_sync(0xffffffffu, p, 8);
                yo[j] = fmaf(Dv, xv, p) * zv;
            }
            if (n == 0)
                *(float4*)&sy[dloc][g] = make_float4(yo[0], yo[1], yo[2], yo[3]);
        }
        __syncthreads();
        {
            int r = tid >> 4, c = (tid & 15) * 4;
            *(float4*)(yout + ((size_t)b * DI + d0 + r) * NS + t0 + c) =
                *(float4*)&sy[r][c];
        }
    }
}

// ---------------------------------------------------------------------------
// tc_op (outproj + residual): res(b,s,dm) += W(256,512) x y(d,s).
// Writes h only on last layer.
// ---------------------------------------------------------------------------
#define OP_ASZ (128 * 36)
#define OP_BSZ (32 * 72)
#define OP_SMEM ((2 * OP_ASZ + 2 * OP_BSZ) * 4)

__global__ __launch_bounds__(256)
void tc_op(const float* __restrict__ W, const float* __restrict__ Y,
           float* __restrict__ RES, float* __restrict__ H, int write_h) {
    extern __shared__ uint32_t sm_op[];
    uint32_t* As = sm_op;
    uint32_t* Bs = sm_op + 2 * OP_ASZ;
    int b = blockIdx.z;
    int m0 = blockIdx.y * 128, s0 = blockIdx.x * 64;
    const float* Yb = Y + (size_t)b * DI * NS;
    int tid = threadIdx.x, lane = tid & 31, wid = tid >> 5;
    int wm = (wid >> 1) * 32, wn = (wid & 1) * 32;
    int gr = lane >> 2, gc = lane & 3;
    float acc[2][4][4];
#pragma unroll
    for (int i = 0; i < 2; i++)
#pragma unroll
        for (int j = 0; j < 4; j++)
#pragma unroll
            for (int q = 0; q < 4; q++) acc[i][j][q] = 0.f;
    int la_m = tid >> 3, la_k = (tid & 7) * 4;
    int bk = tid >> 4, bn4 = (tid & 15) * 4;
    const float* Apt = W + (size_t)(m0 + la_m) * DI + la_k;
    float4 ar[4], br[2];
#pragma unroll
    for (int i = 0; i < 4; i++) ar[i] = *(const float4*)(Apt + (size_t)(i * 32) * DI);
#pragma unroll
    for (int i = 0; i < 2; i++)
        br[i] = *(const float4*)(Yb + (size_t)(bk + i * 16) * NS + s0 + bn4);
    int buf = 0;
#pragma unroll
    for (int i = 0; i < 4; i++)
        *(uint4*)&As[(la_m + i * 32) * 36 + la_k] = cvt4(ar[i]);
#pragma unroll
    for (int i = 0; i < 2; i++)
        *(uint4*)&Bs[(bk + i * 16) * 72 + bn4] = cvt4(br[i]);
    __syncthreads();

    for (int k0 = 32; k0 <= DI; k0 += 32) {
        if (k0 < DI) {
#pragma unroll
            for (int i = 0; i < 4; i++)
                ar[i] = *(const float4*)(Apt + (size_t)(i * 32) * DI + k0);
#pragma unroll
            for (int i = 0; i < 2; i++)
                br[i] = *(const float4*)(Yb + (size_t)(k0 + bk + i * 16) * NS + s0 + bn4);
        }
        const uint32_t* Ab = As + buf * OP_ASZ;
        const uint32_t* Bb = Bs + buf * OP_BSZ;
#pragma unroll
        for (int ks = 0; ks < 4; ks++) {
            int kb = ks * 8;
            uint32_t a[2][4];
#pragma unroll
            for (int mi = 0; mi < 2; mi++) {
                int rb = wm + mi * 16 + gr;
                a[mi][0] = Ab[rb * 36 + kb + gc];
                a[mi][1] = Ab[(rb + 8) * 36 + kb + gc];
                a[mi][2] = Ab[rb * 36 + kb + gc + 4];
                a[mi][3] = Ab[(rb + 8) * 36 + kb + gc + 4];
            }
#pragma unroll
            for (int ni = 0; ni < 4; ni++) {
                int nn = wn + ni * 8 + gr;
                uint32_t b0 = Bb[(kb + gc) * 72 + nn];
                uint32_t b1 = Bb[(kb + gc + 4) * 72 + nn];
#pragma unroll
                for (int mi = 0; mi < 2; mi++)
                    mma_tf32(acc[mi][ni], a[mi], b0, b1);
            }
        }
        if (k0 < DI) {
            int nb2 = buf ^ 1;
#pragma unroll
            for (int i = 0; i < 4; i++)
                *(uint4*)&As[nb2 * OP_ASZ + (la_m + i * 32) * 36 + la_k] = cvt4(ar[i]);
#pragma unroll
            for (int i = 0; i < 2; i++)
                *(uint4*)&Bs[nb2 * OP_BSZ + (bk + i * 16) * 72 + bn4] = cvt4(br[i]);
            __syncthreads();
            buf = nb2;
        }
    }
#pragma unroll
    for (int mi = 0; mi < 2; mi++) {
        int dm = m0 + wm + mi * 16 + gr;
#pragma unroll
        for (int ni = 0; ni < 4; ni++) {
            int s = s0 + wn + ni * 8 + 2 * gc;
            size_t r0 = (size_t)(b * NS + s) * DM;
            size_t r1 = (size_t)(b * NS + s + 1) * DM;
            RES[r0 + dm]     += acc[mi][ni][0];
            RES[r1 + dm]     += acc[mi][ni][1];
            RES[r0 + dm + 8] += acc[mi][ni][2];
            RES[r1 + dm + 8] += acc[mi][ni][3];
            if (write_h) {
                H[r0 + dm]     = acc[mi][ni][0];
                H[r1 + dm]     = acc[mi][ni][1];
                H[r0 + dm + 8] = acc[mi][ni][2];
                H[r1 + dm + 8] = acc[mi][ni][3];
            }
        }
    }
}

// ---------------------------------------------------------------------------
// head
// ---------------------------------------------------------------------------
__global__ __launch_bounds__(256)
void head_kernel(const float* __restrict__ hin, const float* __restrict__ w,
                 float* __restrict__ out) {
    int wid = threadIdx.x >> 5, lane = threadIdx.x & 31;
    int row = blockIdx.x * 8 + wid;
    const float* hp = hin + (size_t)row * DM;
    int c0 = lane * 4, c1 = 128 + lane * 4;
    float4 v0 = *(const float4*)(hp + c0);
    float4 v1 = *(const float4*)(hp + c1);
    float4 w0 = *(const float4*)(w + c0);
    float4 w1 = *(const float4*)(w + c1);
    float s = v0.x*w0.x + v0.y*w0.y + v0.z*w0.z + v0.w*w0.w +
              v1.x*w1.x + v1.y*w1.y + v1.z*w1.z + v1.w*w1.w;
#pragma unroll
    for (int o = 16; o > 0; o >>= 1) s += __shfl_xor_sync(0xffffffffu, s, o);
    if (lane == 0) out[row] = s;
}

// ---------------------------------------------------------------------------
// host
// ---------------------------------------------------------------------------
extern "C" void kernel_launch(void* const* d_in, const int* in_sizes, int n_in,
                              void* d_out, int out_size) {
    const float* x_src     = (const float*)d_in[0];
    const float* in_W      = (const float*)d_in[2];
    const float* norm_w    = (const float*)d_in[3];
    const float* norm_b    = (const float*)d_in[4];
    const float* inproj_W  = (const float*)d_in[5];
    const float* conv_w    = (const float*)d_in[6];
    const float* conv_b    = (const float*)d_in[7];
    const float* xproj_W   = (const float*)d_in[8];
    const float* dtproj_W  = (const float*)d_in[9];
    const float* dtproj_b  = (const float*)d_in[10];
    const float* A_log     = (const float*)d_in[11];
    const float* D_param   = (const float*)d_in[12];
    const float* outproj_W = (const float*)d_in[13];
    const float* out_W     = (const float*)d_in[14];
    float* out = (float*)d_out;

    static int smem_set = 0;
    if (!smem_set) {
        cudaFuncSetAttribute(tc_in, cudaFuncAttributeMaxDynamicSharedMemorySize,
                             NT_SMEM);
        cudaFuncSetAttribute(tc_op, cudaFuncAttributeMaxDynamicSharedMemorySize,
                             OP_SMEM);
        cudaFuncSetAttribute(tc_xp, cudaFuncAttributeMaxDynamicSharedMemorySize,
                             XP_SMEM);
        smem_set = 1;
    }

    float *pres, *ph, *pxt, *pzt, *pxc, *pdblt, *py;
    float2* pstats;
    cudaGetSymbolAddress((void**)&pres,  g_res);
    cudaGetSymbolAddress((void**)&ph,    g_h);
    cudaGetSymbolAddress((void**)&pstats, g_stats);
    cudaGetSymbolAddress((void**)&pxt,   g_xt);
    cudaGetSymbolAddress((void**)&pzt,   g_zt);
    cudaGetSymbolAddress((void**)&pxc,   g_xc);
    cudaGetSymbolAddress((void**)&pdblt, g_dblt);
    cudaGetSymbolAddress((void**)&py,    g_y);

    embed_kernel<<<NTOK, 256>>>(x_src, in_W, pres);

    for (int l = 0; l < 4; l++) {
        stats_kernel<<<NTOK / 8, 256>>>(pres, pstats);
        tc_in<<<dim3(1024 / 64, NTOK / 128), 256, NT_SMEM>>>(
            pres, pstats, norm_w + l * DM, norm_b + l * DM,
            inproj_W + (size_t)l * 1024 * DM, pxt, pzt);
        conv_t<<<dim3(DI, NB), 256>>>(
            pxt, conv_w + (size_t)l * DI * 4, conv_b + (size_t)l * DI, pxc);
        tc_xp<<<dim3(NS / 64, 1, NB), 256, XP_SMEM>>>(
            xproj_W + (size_t)l * 48 * DI, pxc, pdblt);
        scan_kernel<<<dim3(DI / 8, NB), 128>>>(
            pxc, pzt, pdblt,
            dtproj_W + (size_t)l * DI * 16, dtproj_b + (size_t)l * DI,
            A_log + (size_t)l * DI * DSTATE, D_param + (size_t)l * DI, py);
        tc_op<<<dim3(NS / 64, DM / 128, NB), 256, OP_SMEM>>>(
            outproj_W + (size_t)l * DM * DI, py, pres, ph, (l == 3) ? 1 : 0);
    }

    head_kernel<<<NTOK / 8, 256>>>(ph, out_W, out);
}

// round 10
// speedup vs baseline: 1.2131x; 1.1105x over previous
#include <cuda_runtime.h>
#include <cuda_fp16.h>
#include <cstdint>
#include <cstddef>

// ---------------------------------------------------------------------------
// Mamba. R6 skeleton (best) + fp16 storage for big (b,d,s) streams +
// tc_xp re-tiled to fix grid starvation.
// Layouts: h/res/hn (b,s,f) fp32 row-major; xt/zt/xc/y (b,d,s) fp16;
//          dblt (b,j,s) fp32.
// ---------------------------------------------------------------------------

#define NB     4
#define NS     2048
#define DM     256
#define DI     512
#define DSTATE 16
#define NTOK   (NB * NS)

__device__ float  g_h   [NTOK * DM];
__device__ float  g_res [NTOK * DM];
__device__ float  g_hn  [NTOK * DM];
__device__ __half g_xt  [NB * DI * NS];
__device__ __half g_zt  [NB * DI * NS];
__device__ __half g_xc  [NB * DI * NS];
__device__ float  g_dblt[NB * 48 * NS];
__device__ __half g_y   [NB * DI * NS];

// ---------------------------------------------------------------------------
__device__ __forceinline__ uint32_t f2tf(float x) {
    uint32_t u;
    asm("cvt.rna.tf32.f32 %0, %1;" : "=r"(u) : "f"(x));
    return u;
}

__device__ __forceinline__ void mma_tf32(float* c, const uint32_t* a,
                                         uint32_t b0, uint32_t b1) {
    asm volatile(
        "mma.sync.aligned.m16n8k8.row.col.f32.tf32.tf32.f32 "
        "{%0,%1,%2,%3},{%4,%5,%6,%7},{%8,%9},{%0,%1,%2,%3};"
        : "+f"(c[0]), "+f"(c[1]), "+f"(c[2]), "+f"(c[3])
        : "r"(a[0]), "r"(a[1]), "r"(a[2]), "r"(a[3]), "r"(b0), "r"(b1));
}

__device__ __forceinline__ uint4 cvt4(float4 v) {
    uint4 u;
    u.x = f2tf(v.x); u.y = f2tf(v.y); u.z = f2tf(v.z); u.w = f2tf(v.w);
    return u;
}

__device__ __forceinline__ float silu_f(float x) {
    return x / (1.f + __expf(-x));
}

__device__ __forceinline__ float softplus_f(float x) {
    return (x > 20.f) ? x : log1pf(__expf(x));
}

// fp16 vector helpers (8B = 4 halves)
__device__ __forceinline__ float4 ldh4(const __half* p) {
    uint2 u = *(const uint2*)p;
    __half2 h0 = *reinterpret_cast<__half2*>(&u.x);
    __half2 h1 = *reinterpret_cast<__half2*>(&u.y);
    float2 f0 = __half22float2(h0), f1 = __half22float2(h1);
    return make_float4(f0.x, f0.y, f1.x, f1.y);
}

__device__ __forceinline__ void sth4(__half* p, float4 v) {
    __half2 h0 = __floats2half2_rn(v.x, v.y);
    __half2 h1 = __floats2half2_rn(v.z, v.w);
    uint2 u;
    u.x = *reinterpret_cast<uint32_t*>(&h0);
    u.y = *reinterpret_cast<uint32_t*>(&h1);
    *(uint2*)p = u;
}

// ---------------------------------------------------------------------------
// embed -> h
// ---------------------------------------------------------------------------
__global__ __launch_bounds__(256)
void embed_kernel(const float* __restrict__ x, const float* __restrict__ W,
                  float* __restrict__ h) {
    __shared__ float xs[15];
    int row = blockIdx.x;
    if (threadIdx.x < 15) xs[threadIdx.x] = x[row * 15 + threadIdx.x];
    __syncthreads();
    int m = threadIdx.x;
    const float* wr = W + m * 15;
    float acc = 0.f;
#pragma unroll
    for (int k = 0; k < 15; k++) acc = fmaf(xs[k], wr[k], acc);
    h[(size_t)row * DM + m] = acc;
}

// ---------------------------------------------------------------------------
// fused residual + layernorm; one warp per row of 256
// ---------------------------------------------------------------------------
__global__ __launch_bounds__(256)
void ln_kernel(const float* __restrict__ hin, float* __restrict__ res,
               float* __restrict__ hn, const float* __restrict__ w,
               const float* __restrict__ bb, int first) {
    int wid = threadIdx.x >> 5, lane = threadIdx.x & 31;
    int row = blockIdx.x * 8 + wid;
    const float* hp = hin + (size_t)row * DM;
    float* rp = res + (size_t)row * DM;
    float* op = hn + (size_t)row * DM;
    int c0 = lane * 4, c1 = 128 + lane * 4;
    float4 v0 = *(const float4*)(hp + c0);
    float4 v1 = *(const float4*)(hp + c1);
    if (!first) {
        float4 r0 = *(const float4*)(rp + c0);
        float4 r1 = *(const float4*)(rp + c1);
        v0.x += r0.x; v0.y += r0.y; v0.z += r0.z; v0.w += r0.w;
        v1.x += r1.x; v1.y += r1.y; v1.z += r1.z; v1.w += r1.w;
    }
    *(float4*)(rp + c0) = v0;
    *(float4*)(rp + c1) = v1;
    float s = v0.x + v0.y + v0.z + v0.w + v1.x + v1.y + v1.z + v1.w;
    float q = v0.x*v0.x + v0.y*v0.y + v0.z*v0.z + v0.w*v0.w +
              v1.x*v1.x + v1.y*v1.y + v1.z*v1.z + v1.w*v1.w;
#pragma unroll
    for (int o = 16; o > 0; o >>= 1) {
        s += __shfl_xor_sync(0xffffffffu, s, o);
        q += __shfl_xor_sync(0xffffffffu, q, o);
    }
    float m  = s * (1.f / 256.f);
    float var = q * (1.f / 256.f) - m * m;
    float rstd = rsqrtf(var + 1e-5f);
    float4 w0 = *(const float4*)(w + c0), w1 = *(const float4*)(w + c1);
    float4 b0 = *(const float4*)(bb + c0), b1 = *(const float4*)(bb + c1);
    float4 o0, o1;
    o0.x = (v0.x - m) * rstd * w0.x + b0.x;
    o0.y = (v0.y - m) * rstd * w0.y + b0.y;
    o0.z = (v0.z - m) * rstd * w0.z + b0.z;
    o0.w = (v0.w - m) * rstd * w0.w + b0.w;
    o1.x = (v1.x - m) * rstd * w1.x + b1.x;
    o1.y = (v1.y - m) * rstd * w1.y + b1.y;
    o1.z = (v1.z - m) * rstd * w1.z + b1.z;
    o1.w = (v1.w - m) * rstd * w1.w + b1.w;
    *(float4*)(op + c0) = o0;
    *(float4*)(op + c1) = o1;
}

// ---------------------------------------------------------------------------
// tc_in (inproj): xz = hn(8192,256) * W(1024,256)^T; transpose epilogue to
// fp16: feat<512 -> xt raw; >=512 -> zt silu'd.
// ---------------------------------------------------------------------------
#define NT_ASZ (128 * 36)
#define NT_BSZ (64 * 36)
#define NT_SMEM ((2 * NT_ASZ + 2 * NT_BSZ) * 4)

__global__ __launch_bounds__(256)
void tc_in(const float* __restrict__ A, const float* __restrict__ B,
           __half* __restrict__ xt, __half* __restrict__ zt) {
    const int K = DM;
    extern __shared__ uint32_t sm_nt[];
    uint32_t* As = sm_nt;
    uint32_t* Bs = sm_nt + 2 * NT_ASZ;
    int tid = threadIdx.x, lane = tid & 31, wid = tid >> 5;
    int m0 = blockIdx.y * 128, n0 = blockIdx.x * 64;
    int wm = (wid >> 1) * 32, wn = (wid & 1) * 32;
    int gr = lane >> 2, gc = lane & 3;
    float acc[2][4][4];
#pragma unroll
    for (int i = 0; i < 2; i++)
#pragma unroll
        for (int j = 0; j < 4; j++)
#pragma unroll
            for (int q = 0; q < 4; q++) acc[i][j][q] = 0.f;
    int la_m = tid >> 3, la_k = (tid & 7) * 4;
    int lb_n = tid >> 2, lb_k = (tid & 3) * 8;
    const float* Apt = A + (size_t)(m0 + la_m) * K + la_k;
    const float* Bpt = B + (size_t)(n0 + lb_n) * K + lb_k;
    float4 ar[4], br[2];
#pragma unroll
    for (int i = 0; i < 4; i++) ar[i] = *(const float4*)(Apt + (size_t)(i * 32) * K);
    br[0] = *(const float4*)(Bpt);
    br[1] = *(const float4*)(Bpt + 4);
    int buf = 0;
#pragma unroll
    for (int i = 0; i < 4; i++)
        *(uint4*)&As[(la_m + i * 32) * 36 + la_k] = cvt4(ar[i]);
    *(uint4*)&Bs[lb_n * 36 + lb_k]     = cvt4(br[0]);
    *(uint4*)&Bs[lb_n * 36 + lb_k + 4] = cvt4(br[1]);
    __syncthreads();

    for (int k0 = 32; k0 <= K; k0 += 32) {
        if (k0 < K) {
#pragma unroll
            for (int i = 0; i < 4; i++)
                ar[i] = *(const float4*)(Apt + (size_t)(i * 32) * K + k0);
            br[0] = *(const float4*)(Bpt + k0);
            br[1] = *(const float4*)(Bpt + k0 + 4);
        }
        const uint32_t* Ab = As + buf * NT_ASZ;
        const uint32_t* Bb = Bs + buf * NT_BSZ;
#pragma unroll
        for (int ks = 0; ks < 4; ks++) {
            int kb = ks * 8;
            uint32_t a[2][4];
#pragma unroll
            for (int mi = 0; mi < 2; mi++) {
                int rb = wm + mi * 16 + gr;
                a[mi][0] = Ab[rb * 36 + kb + gc];
                a[mi][1] = Ab[(rb + 8) * 36 + kb + gc];
                a[mi][2] = Ab[rb * 36 + kb + gc + 4];
                a[mi][3] = Ab[(rb + 8) * 36 + kb + gc + 4];
            }
#pragma unroll
            for (int ni = 0; ni < 4; ni++) {
                uint32_t b0 = Bb[(wn + ni * 8 + gr) * 36 + kb + gc];
                uint32_t b1 = Bb[(wn + ni * 8 + gr) * 36 + kb + gc + 4];
#pragma unroll
                for (int mi = 0; mi < 2; mi++)
                    mma_tf32(acc[mi][ni], a[mi], b0, b1);
            }
        }
        if (k0 < K) {
            int nb2 = buf ^ 1;
#pragma unroll
            for (int i = 0; i < 4; i++)
                *(uint4*)&As[nb2 * NT_ASZ + (la_m + i * 32) * 36 + la_k] = cvt4(ar[i]);
            *(uint4*)&Bs[nb2 * NT_BSZ + lb_n * 36 + lb_k]     = cvt4(br[0]);
            *(uint4*)&Bs[nb2 * NT_BSZ + lb_n * 36 + lb_k + 4] = cvt4(br[1]);
            __syncthreads();
            buf = nb2;
        }
    }
    // transpose epilogue via smem: st[feat][tok], stride 132
    float* st = (float*)sm_nt;
    __syncthreads();
#pragma unroll
    for (int mi = 0; mi < 2; mi++) {
        int r0 = wm + mi * 16 + gr;
#pragma unroll
        for (int ni = 0; ni < 4; ni++) {
            int cc = wn + ni * 8 + 2 * gc;
            st[cc * 132 + r0]           = acc[mi][ni][0];
            st[(cc + 1) * 132 + r0]     = acc[mi][ni][1];
            st[cc * 132 + r0 + 8]       = acc[mi][ni][2];
            st[(cc + 1) * 132 + r0 + 8] = acc[mi][ni][3];
        }
    }
    __syncthreads();
    int b = m0 / NS, s0 = m0 % NS;
#pragma unroll
    for (int rr = wid; rr < 64; rr += 8) {
        int f = n0 + rr;
        float4 v = *(float4*)&st[rr * 132 + lane * 4];
        if (f < DI) {
            sth4(xt + ((size_t)b * DI + f) * NS + s0 + lane * 4, v);
        } else {
            v.x = silu_f(v.x); v.y = silu_f(v.y);
            v.z = silu_f(v.z); v.w = silu_f(v.w);
            sth4(zt + ((size_t)b * DI + f - DI) * NS + s0 + lane * 4, v);
        }
    }
}

// ---------------------------------------------------------------------------
// conv_t: causal 4-tap depthwise conv + SiLU, fp16 in/out, streaming.
// ---------------------------------------------------------------------------
__global__ __launch_bounds__(256)
void conv_t(const __half* __restrict__ xt, const float* __restrict__ cw,
            const float* __restrict__ cb, __half* __restrict__ xc) {
    int d = blockIdx.x, b = blockIdx.y;
    const __half* row = xt + ((size_t)b * DI + d) * NS;
    __half* orow = xc + ((size_t)b * DI + d) * NS;
    float w0 = cw[d * 4 + 0], w1 = cw[d * 4 + 1];
    float w2 = cw[d * 4 + 2], w3 = cw[d * 4 + 3];
    float bias = cb[d];
    int s = threadIdx.x * 8;
    float in[12];
    float4 A = (s == 0) ? make_float4(0.f, 0.f, 0.f, 0.f) : ldh4(row + s - 4);
    float4 Bv = ldh4(row + s);
    float4 Cv = ldh4(row + s + 4);
    in[0] = A.x; in[1] = A.y; in[2] = A.z; in[3] = A.w;
    in[4] = Bv.x; in[5] = Bv.y; in[6] = Bv.z; in[7] = Bv.w;
    in[8] = Cv.x; in[9] = Cv.y; in[10] = Cv.z; in[11] = Cv.w;
    float o[8];
#pragma unroll
    for (int k = 0; k < 8; k++) {
        float a = bias + w0 * in[k + 1] + w1 * in[k + 2]
                       + w2 * in[k + 3] + w3 * in[k + 4];
        o[k] = silu_f(a);
    }
    sth4(orow + s,     make_float4(o[0], o[1], o[2], o[3]));
    sth4(orow + s + 4, make_float4(o[4], o[5], o[6], o[7]));
}

// ---------------------------------------------------------------------------
// tc_xp (xproj): per batch, dblt(48, s) = xpW(48,512) x xc(d,s); K=512.
// Re-tiled: s-tile 32 -> 256 blocks (was 128; grid-starved at 148 SMs).
// 8 warps as 2(m)x4(n), warp tile 32(m)x8(s).
// ---------------------------------------------------------------------------
#define XP_ASZ (64 * 36)
#define XP_BSZ (32 * 40)
#define XP_SMEM ((2 * XP_ASZ + 2 * XP_BSZ) * 4)

__global__ __launch_bounds__(256)
void tc_xp(const float* __restrict__ W, const __half* __restrict__ X,
           float* __restrict__ Dt) {
    extern __shared__ uint32_t sm_xp[];
    uint32_t* As = sm_xp;
    uint32_t* Bs = sm_xp + 2 * XP_ASZ;
    int b = blockIdx.z;
    int s0 = blockIdx.x * 32;
    const __half* Xb = X + (size_t)b * DI * NS;
    float* Db = Dt + (size_t)b * 48 * NS;
    int tid = threadIdx.x, lane = tid & 31, wid = tid >> 5;
    int wm = (wid >> 2) * 32, wn = (wid & 3) * 8;
    int gr = lane >> 2, gc = lane & 3;
    float acc[2][4];
#pragma unroll
    for (int i = 0; i < 2; i++)
#pragma unroll
        for (int q = 0; q < 4; q++) acc[i][q] = 0.f;
    int la_m = tid >> 2, la_k = (tid & 3) * 8;    // A: row la_m (0..63), 2 f4
    int bk = tid >> 3, bn4 = (tid & 7) * 4;       // B: row bk (0..31), 1 h4
    bool avalid = (la_m < 48);
    const float* Apt = W + (size_t)la_m * DI + la_k;
    float4 zero = make_float4(0.f, 0.f, 0.f, 0.f);
    float4 ar[2], br;
    ar[0] = avalid ? *(const float4*)(Apt)     : zero;
    ar[1] = avalid ? *(const float4*)(Apt + 4) : zero;
    br = ldh4(Xb + (size_t)bk * NS + s0 + bn4);
    int buf = 0;
    *(uint4*)&As[la_m * 36 + la_k]     = cvt4(ar[0]);
    *(uint4*)&As[la_m * 36 + la_k + 4] = cvt4(ar[1]);
    *(uint4*)&Bs[bk * 40 + bn4] = cvt4(br);
    __syncthreads();

    for (int k0 = 32; k0 <= DI; k0 += 32) {
        if (k0 < DI) {
            ar[0] = avalid ? *(const float4*)(Apt + k0)     : zero;
            ar[1] = avalid ? *(const float4*)(Apt + k0 + 4) : zero;
            br = ldh4(Xb + (size_t)(k0 + bk) * NS + s0 + bn4);
        }
        const uint32_t* Ab = As + buf * XP_ASZ;
        const uint32_t* Bb = Bs + buf * XP_BSZ;
#pragma unroll
        for (int ks = 0; ks < 4; ks++) {
            int kb = ks * 8;
            uint32_t a[2][4];
#pragma unroll
            for (int mi = 0; mi < 2; mi++) {
                int rb = wm + mi * 16 + gr;
                a[mi][0] = Ab[rb * 36 + kb + gc];
                a[mi][1] = Ab[(rb + 8) * 36 + kb + gc];
                a[mi][2] = Ab[rb * 36 + kb + gc + 4];
                a[mi][3] = Ab[(rb + 8) * 36 + kb + gc + 4];
            }
            int nn = wn + gr;
            uint32_t b0 = Bb[(kb + gc) * 40 + nn];
            uint32_t b1 = Bb[(kb + gc + 4) * 40 + nn];
#pragma unroll
            for (int mi = 0; mi < 2; mi++)
                mma_tf32(acc[mi], a[mi], b0, b1);
        }
        if (k0 < DI) {
            int nb2 = buf ^ 1;
            *(uint4*)&As[nb2 * XP_ASZ + la_m * 36 + la_k]     = cvt4(ar[0]);
            *(uint4*)&As[nb2 * XP_ASZ + la_m * 36 + la_k + 4] = cvt4(ar[1]);
            *(uint4*)&Bs[nb2 * XP_BSZ + bk * 40 + bn4] = cvt4(br);
            __syncthreads();
            buf = nb2;
        }
    }
#pragma unroll
    for (int mi = 0; mi < 2; mi++) {
        int m = wm + mi * 16 + gr;
        int sc = s0 + wn + 2 * gc;
        if (m < 48)
            *(float2*)(Db + (size_t)m * NS + sc) =
                make_float2(acc[mi][0], acc[mi][1]);
        if (m + 8 < 48)
            *(float2*)(Db + (size_t)(m + 8) * NS + sc) =
                make_float2(acc[mi][2], acc[mi][3]);
    }
}

// ---------------------------------------------------------------------------
// scan: fused dtproj + chunked smem staging. 128 threads = 8 channels.
// x/z read fp16, y written fp16; dblt fp32.
// ---------------------------------------------------------------------------
#define SCH 64

__global__ __launch_bounds__(128)
void scan_kernel(const __half* __restrict__ xcp, const __half* __restrict__ ztp,
                 const float* __restrict__ dblt,
                 const float* __restrict__ dtW, const float* __restrict__ dtb,
                 const float* __restrict__ Alog, const float* __restrict__ Dp,
                 __half* __restrict__ yout) {
    __shared__ float sdp[16][SCH];
    __shared__ float sB [16][SCH + 4];
    __shared__ float sC [16][SCH + 4];
    __shared__ float sdt[8][SCH + 4];
    __shared__ float sx [8][SCH + 4];
    __shared__ float sz [8][SCH + 4];
    __shared__ float sy [8][SCH + 4];
    __shared__ float sW [8][16];
    __shared__ float sbias[8];

    int b = blockIdx.y;
    int d0 = blockIdx.x * 8;
    int tid = threadIdx.x, lane = tid & 31, warp = tid >> 5;
    int dl = lane >> 4, n = lane & 15;
    int dloc = warp * 2 + dl;
    int d = d0 + dloc;

    {
        int dd = tid >> 4, j = tid & 15;
        sW[dd][j] = dtW[(size_t)(d0 + dd) * 16 + j];
    }
    if (tid < 8) sbias[tid] = dtb[d0 + tid];

    float a  = -__expf(Alog[d * DSTATE + n]);
    float Dv = Dp[d];
    float hst = 0.f;
    const float* dpb = dblt + (size_t)b * 48 * NS;

    for (int t0 = 0; t0 < NS; t0 += SCH) {
        {
            int r = tid >> 3, c = (tid & 7) * 8;
            *(float4*)&sdp[r][c]     = *(const float4*)(dpb + (size_t)r * NS + t0 + c);
            *(float4*)&sdp[r][c + 4] = *(const float4*)(dpb + (size_t)r * NS + t0 + c + 4);
            *(float4*)&sB[r][c]      = *(const float4*)(dpb + (size_t)(16 + r) * NS + t0 + c);
            *(float4*)&sB[r][c + 4]  = *(const float4*)(dpb + (size_t)(16 + r) * NS + t0 + c + 4);
            *(float4*)&sC[r][c]      = *(const float4*)(dpb + (size_t)(32 + r) * NS + t0 + c);
            *(float4*)&sC[r][c + 4]  = *(const float4*)(dpb + (size_t)(32 + r) * NS + t0 + c + 4);
        }
        {
            int r = tid >> 4, c = (tid & 15) * 4;
            *(float4*)&sx[r][c] = ldh4(xcp + ((size_t)b * DI + d0 + r) * NS + t0 + c);
            *(float4*)&sz[r][c] = ldh4(ztp + ((size_t)b * DI + d0 + r) * NS + t0 + c);
        }
        __syncthreads();
        {
            int dd = tid >> 4, tt = (tid & 15) * 4;
            float bi = sbias[dd];
            float a0 = bi, a1 = bi, a2 = bi, a3 = bi;
#pragma unroll
            for (int j = 0; j < 16; j++) {
                float w = sW[dd][j];
                a0 = fmaf(w, sdp[j][tt],     a0);
                a1 = fmaf(w, sdp[j][tt + 1], a1);
                a2 = fmaf(w, sdp[j][tt + 2], a2);
                a3 = fmaf(w, sdp[j][tt + 3], a3);
            }
            sdt[dd][tt]     = softplus_f(a0);
            sdt[dd][tt + 1] = softplus_f(a1);
            sdt[dd][tt + 2] = softplus_f(a2);
            sdt[dd][tt + 3] = softplus_f(a3);
        }
        __syncthreads();
        for (int g = 0; g < SCH; g += 4) {
            float4 dt4 = *(const float4*)&sdt[dloc][g];
            float4 x4  = *(const float4*)&sx[dloc][g];
            float4 z4  = *(const float4*)&sz[dloc][g];
            float4 B4  = *(const float4*)&sB[n][g];
            float4 C4  = *(const float4*)&sC[n][g];
            float yo[4];
#pragma unroll
            for (int j = 0; j < 4; j++) {
                float dtv = (&dt4.x)[j], xv = (&x4.x)[j], zv = (&z4.x)[j];
                float Bv = (&B4.x)[j], Cv = (&C4.x)[j];
                float dA = __expf(dtv * a);
                hst = fmaf(dA, hst, dtv * xv * Bv);
                float p = hst * Cv;
                p += __shfl_xor_sync(0xffffffffu, p, 1);
                p += __shfl_xor_sync(0xffffffffu, p, 2);
                p += __shfl_xor_sync(0xffffffffu, p, 4);
                p += __shfl_xor_sync(0xffffffffu, p, 8);
                yo[j] = fmaf(Dv, xv, p) * zv;
            }
            if (n == 0)
                *(float4*)&sy[dloc][g] = make_float4(yo[0], yo[1], yo[2], yo[3]);
        }
        __syncthreads();
        {
            int r = tid >> 4, c = (tid & 15) * 4;
            sth4(yout + ((size_t)b * DI + d0 + r) * NS + t0 + c,
                 *(float4*)&sy[r][c]);
        }
        __syncthreads();
    }
}

// ---------------------------------------------------------------------------
// tc_op (outproj): per batch, h(s,dm) = W(256,512) x y(d,s); K=512.
// y fp16. Scatter epilogue into h (b,s,dm).
// ---------------------------------------------------------------------------
#define OP_ASZ (128 * 36)
#define OP_BSZ (32 * 72)
#define OP_SMEM ((2 * OP_ASZ + 2 * OP_BSZ) * 4)

__global__ __launch_bounds__(256)
void tc_op(const float* __restrict__ W, const __half* __restrict__ Y,
           float* __restrict__ H) {
    extern __shared__ uint32_t sm_op[];
    uint32_t* As = sm_op;
    uint32_t* Bs = sm_op + 2 * OP_ASZ;
    int b = blockIdx.z;
    int m0 = blockIdx.y * 128, s0 = blockIdx.x * 64;
    const __half* Yb = Y + (size_t)b * DI * NS;
    int tid = threadIdx.x, lane = tid & 31, wid = tid >> 5;
    int wm = (wid >> 1) * 32, wn = (wid & 1) * 32;
    int gr = lane >> 2, gc = lane & 3;
    float acc[2][4][4];
#pragma unroll
    for (int i = 0; i < 2; i++)
#pragma unroll
        for (int j = 0; j < 4; j++)
#pragma unroll
            for (int q = 0; q < 4; q++) acc[i][j][q] = 0.f;
    int la_m = tid >> 3, la_k = (tid & 7) * 4;
    int bk = tid >> 4, bn4 = (tid & 15) * 4;
    const float* Apt = W + (size_t)(m0 + la_m) * DI + la_k;
    float4 ar[4], br[2];
#pragma unroll
    for (int i = 0; i < 4; i++) ar[i] = *(const float4*)(Apt + (size_t)(i * 32) * DI);
#pragma unroll
    for (int i = 0; i < 2; i++)
        br[i] = ldh4(Yb + (size_t)(bk + i * 16) * NS + s0 + bn4);
    int buf = 0;
#pragma unroll
    for (int i = 0; i < 4; i++)
        *(uint4*)&As[(la_m + i * 32) * 36 + la_k] = cvt4(ar[i]);
#pragma unroll
    for (int i = 0; i < 2; i++)
        *(uint4*)&Bs[(bk + i * 16) * 72 + bn4] = cvt4(br[i]);
    __syncthreads();

    for (int k0 = 32; k0 <= DI; k0 += 32) {
        if (k0 < DI) {
#pragma unroll
            for (int i = 0; i < 4; i++)
                ar[i] = *(const float4*)(Apt + (size_t)(i * 32) * DI + k0);
#pragma unroll
            for (int i = 0; i < 2; i++)
                br[i] = ldh4(Yb + (size_t)(k0 + bk + i * 16) * NS + s0 + bn4);
        }
        const uint32_t* Ab = As + buf * OP_ASZ;
        const uint32_t* Bb = Bs + buf * OP_BSZ;
#pragma unroll
        for (int ks = 0; ks < 4; ks++) {
            int kb = ks * 8;
            uint32_t a[2][4];
#pragma unroll
            for (int mi = 0; mi < 2; mi++) {
                int rb = wm + mi * 16 + gr;
                a[mi][0] = Ab[rb * 36 + kb + gc];
                a[mi][1] = Ab[(rb + 8) * 36 + kb + gc];
                a[mi][2] = Ab[rb * 36 + kb + gc + 4];
                a[mi][3] = Ab[(rb + 8) * 36 + kb + gc + 4];
            }
#pragma unroll
            for (int ni = 0; ni < 4; ni++) {
                int nn = wn + ni * 8 + gr;
                uint32_t b0 = Bb[(kb + gc) * 72 + nn];
                uint32_t b1 = Bb[(kb + gc + 4) * 72 + nn];
#pragma unroll
                for (int mi = 0; mi < 2; mi++)
                    mma_tf32(acc[mi][ni], a[mi], b0, b1);
            }
        }
        if (k0 < DI) {
            int nb2 = buf ^ 1;
#pragma unroll
            for (int i = 0; i < 4; i++)
                *(uint4*)&As[nb2 * OP_ASZ + (la_m + i * 32) * 36 + la_k] = cvt4(ar[i]);
#pragma unroll
            for (int i = 0; i < 2; i++)
                *(uint4*)&Bs[nb2 * OP_BSZ + (bk + i * 16) * 72 + bn4] = cvt4(br[i]);
            __syncthreads();
            buf = nb2;
        }
    }
#pragma unroll
    for (int mi = 0; mi < 2; mi++) {
        int dm = m0 + wm + mi * 16 + gr;
#pragma unroll
        for (int ni = 0; ni < 4; ni++) {
            int s = s0 + wn + ni * 8 + 2 * gc;
            size_t r0 = (size_t)(b * NS + s) * DM;
            size_t r1 = (size_t)(b * NS + s + 1) * DM;
            H[r0 + dm]     = acc[mi][ni][0];
            H[r1 + dm]     = acc[mi][ni][1];
            H[r0 + dm + 8] = acc[mi][ni][2];
            H[r1 + dm + 8] = acc[mi][ni][3];
        }
    }
}

// ---------------------------------------------------------------------------
// head
// ---------------------------------------------------------------------------
__global__ __launch_bounds__(256)
void head_kernel(const float* __restrict__ hin, const float* __restrict__ w,
                 float* __restrict__ out) {
    int wid = threadIdx.x >> 5, lane = threadIdx.x & 31;
    int row = blockIdx.x * 8 + wid;
    const float* hp = hin + (size_t)row * DM;
    int c0 = lane * 4, c1 = 128 + lane * 4;
    float4 v0 = *(const float4*)(hp + c0);
    float4 v1 = *(const float4*)(hp + c1);
    float4 w0 = *(const float4*)(w + c0);
    float4 w1 = *(const float4*)(w + c1);
    float s = v0.x*w0.x + v0.y*w0.y + v0.z*w0.z + v0.w*w0.w +
              v1.x*w1.x + v1.y*w1.y + v1.z*w1.z + v1.w*w1.w;
#pragma unroll
    for (int o = 16; o > 0; o >>= 1) s += __shfl_xor_sync(0xffffffffu, s, o);
    if (lane == 0) out[row] = s;
}

// ---------------------------------------------------------------------------
// host
// ---------------------------------------------------------------------------
extern "C" void kernel_launch(void* const* d_in, const int* in_sizes, int n_in,
                              void* d_out, int out_size) {
    const float* x_src     = (const float*)d_in[0];
    const float* in_W      = (const float*)d_in[2];
    const float* norm_w    = (const float*)d_in[3];
    const float* norm_b    = (const float*)d_in[4];
    const float* inproj_W  = (const float*)d_in[5];
    const float* conv_w    = (const float*)d_in[6];
    const float* conv_b    = (const float*)d_in[7];
    const float* xproj_W   = (const float*)d_in[8];
    const float* dtproj_W  = (const float*)d_in[9];
    const float* dtproj_b  = (const float*)d_in[10];
    const float* A_log     = (const float*)d_in[11];
    const float* D_param   = (const float*)d_in[12];
    const float* outproj_W = (const float*)d_in[13];
    const float* out_W     = (const float*)d_in[14];
    float* out = (float*)d_out;

    static int smem_set = 0;
    if (!smem_set) {
        cudaFuncSetAttribute(tc_in, cudaFuncAttributeMaxDynamicSharedMemorySize,
                             NT_SMEM);
        cudaFuncSetAttribute(tc_op, cudaFuncAttributeMaxDynamicSharedMemorySize,
                             OP_SMEM);
        cudaFuncSetAttribute(tc_xp, cudaFuncAttributeMaxDynamicSharedMemorySize,
                             XP_SMEM);
        smem_set = 1;
    }

    float *ph, *pres, *phn, *pdblt;
    __half *pxt, *pzt, *pxc, *py;
    cudaGetSymbolAddress((void**)&ph,    g_h);
    cudaGetSymbolAddress((void**)&pres,  g_res);
    cudaGetSymbolAddress((void**)&phn,   g_hn);
    cudaGetSymbolAddress((void**)&pxt,   g_xt);
    cudaGetSymbolAddress((void**)&pzt,   g_zt);
    cudaGetSymbolAddress((void**)&pxc,   g_xc);
    cudaGetSymbolAddress((void**)&pdblt, g_dblt);
    cudaGetSymbolAddress((void**)&py,    g_y);

    embed_kernel<<<NTOK, 256>>>(x_src, in_W, ph);

    for (int l = 0; l < 4; l++) {
        ln_kernel<<<NTOK / 8, 256>>>(ph, pres, phn,
                                     norm_w + l * DM, norm_b + l * DM,
                                     (l == 0) ? 1 : 0);
        tc_in<<<dim3(1024 / 64, NTOK / 128), 256, NT_SMEM>>>(
            phn, inproj_W + (size_t)l * 1024 * DM, pxt, pzt);
        conv_t<<<dim3(DI, NB), 256>>>(
            pxt, conv_w + (size_t)l * DI * 4, conv_b + (size_t)l * DI, pxc);
        tc_xp<<<dim3(NS / 32, 1, NB), 256, XP_SMEM>>>(
            xproj_W + (size_t)l * 48 * DI, pxc, pdblt);
        scan_kernel<<<dim3(DI / 8, NB), 128>>>(
            pxc, pzt, pdblt,
            dtproj_W + (size_t)l * DI * 16, dtproj_b + (size_t)l * DI,
            A_log + (size_t)l * DI * DSTATE, D_param + (size_t)l * DI, py);
        tc_op<<<dim3(NS / 64, DM / 128, NB), 256, OP_SMEM>>>(
            outproj_W + (size_t)l * DM * DI, py, ph);
    }

    head_kernel<<<NTOK / 8, 256>>>(ph, out_W, out);
}

// round 11
// speedup vs baseline: 1.2442x; 1.0256x over previous
#include <cuda_runtime.h>
#include <cuda_fp16.h>
#include <cstdint>
#include <cstddef>

// ---------------------------------------------------------------------------
// Mamba. R9 skeleton + (a) scan software-pipelined chunk staging,
// (b) hn stored fp16 (double-rounding-neutral vs tf32 GEMM input).
// Layouts: h/res (b,s,f) fp32; hn (b,s,f) fp16; xt/zt/xc/y (b,d,s) fp16;
//          dblt (b,j,s) fp32.
// ---------------------------------------------------------------------------

#define NB     4
#define NS     2048
#define DM     256
#define DI     512
#define DSTATE 16
#define NTOK   (NB * NS)

__device__ float  g_h   [NTOK * DM];
__device__ float  g_res [NTOK * DM];
__device__ __half g_hn  [NTOK * DM];
__device__ __half g_xt  [NB * DI * NS];
__device__ __half g_zt  [NB * DI * NS];
__device__ __half g_xc  [NB * DI * NS];
__device__ float  g_dblt[NB * 48 * NS];
__device__ __half g_y   [NB * DI * NS];

// ---------------------------------------------------------------------------
__device__ __forceinline__ uint32_t f2tf(float x) {
    uint32_t u;
    asm("cvt.rna.tf32.f32 %0, %1;" : "=r"(u) : "f"(x));
    return u;
}

__device__ __forceinline__ void mma_tf32(float* c, const uint32_t* a,
                                         uint32_t b0, uint32_t b1) {
    asm volatile(
        "mma.sync.aligned.m16n8k8.row.col.f32.tf32.tf32.f32 "
        "{%0,%1,%2,%3},{%4,%5,%6,%7},{%8,%9},{%0,%1,%2,%3};"
        : "+f"(c[0]), "+f"(c[1]), "+f"(c[2]), "+f"(c[3])
        : "r"(a[0]), "r"(a[1]), "r"(a[2]), "r"(a[3]), "r"(b0), "r"(b1));
}

__device__ __forceinline__ uint4 cvt4(float4 v) {
    uint4 u;
    u.x = f2tf(v.x); u.y = f2tf(v.y); u.z = f2tf(v.z); u.w = f2tf(v.w);
    return u;
}

__device__ __forceinline__ float silu_f(float x) {
    return x / (1.f + __expf(-x));
}

__device__ __forceinline__ float softplus_f(float x) {
    return (x > 20.f) ? x : log1pf(__expf(x));
}

// fp16 vector helpers (8B = 4 halves)
__device__ __forceinline__ float4 ldh4(const __half* p) {
    uint2 u = *(const uint2*)p;
    __half2 h0 = *reinterpret_cast<__half2*>(&u.x);
    __half2 h1 = *reinterpret_cast<__half2*>(&u.y);
    float2 f0 = __half22float2(h0), f1 = __half22float2(h1);
    return make_float4(f0.x, f0.y, f1.x, f1.y);
}

__device__ __forceinline__ void sth4(__half* p, float4 v) {
    __half2 h0 = __floats2half2_rn(v.x, v.y);
    __half2 h1 = __floats2half2_rn(v.z, v.w);
    uint2 u;
    u.x = *reinterpret_cast<uint32_t*>(&h0);
    u.y = *reinterpret_cast<uint32_t*>(&h1);
    *(uint2*)p = u;
}

// ---------------------------------------------------------------------------
// embed -> h
// ---------------------------------------------------------------------------
__global__ __launch_bounds__(256)
void embed_kernel(const float* __restrict__ x, const float* __restrict__ W,
                  float* __restrict__ h) {
    __shared__ float xs[15];
    int row = blockIdx.x;
    if (threadIdx.x < 15) xs[threadIdx.x] = x[row * 15 + threadIdx.x];
    __syncthreads();
    int m = threadIdx.x;
    const float* wr = W + m * 15;
    float acc = 0.f;
#pragma unroll
    for (int k = 0; k < 15; k++) acc = fmaf(xs[k], wr[k], acc);
    h[(size_t)row * DM + m] = acc;
}

// ---------------------------------------------------------------------------
// fused residual + layernorm; hn written fp16
// ---------------------------------------------------------------------------
__global__ __launch_bounds__(256)
void ln_kernel(const float* __restrict__ hin, float* __restrict__ res,
               __half* __restrict__ hn, const float* __restrict__ w,
               const float* __restrict__ bb, int first) {
    int wid = threadIdx.x >> 5, lane = threadIdx.x & 31;
    int row = blockIdx.x * 8 + wid;
    const float* hp = hin + (size_t)row * DM;
    float* rp = res + (size_t)row * DM;
    __half* op = hn + (size_t)row * DM;
    int c0 = lane * 4, c1 = 128 + lane * 4;
    float4 v0 = *(const float4*)(hp + c0);
    float4 v1 = *(const float4*)(hp + c1);
    if (!first) {
        float4 r0 = *(const float4*)(rp + c0);
        float4 r1 = *(const float4*)(rp + c1);
        v0.x += r0.x; v0.y += r0.y; v0.z += r0.z; v0.w += r0.w;
        v1.x += r1.x; v1.y += r1.y; v1.z += r1.z; v1.w += r1.w;
    }
    *(float4*)(rp + c0) = v0;
    *(float4*)(rp + c1) = v1;
    float s = v0.x + v0.y + v0.z + v0.w + v1.x + v1.y + v1.z + v1.w;
    float q = v0.x*v0.x + v0.y*v0.y + v0.z*v0.z + v0.w*v0.w +
              v1.x*v1.x + v1.y*v1.y + v1.z*v1.z + v1.w*v1.w;
#pragma unroll
    for (int o = 16; o > 0; o >>= 1) {
        s += __shfl_xor_sync(0xffffffffu, s, o);
        q += __shfl_xor_sync(0xffffffffu, q, o);
    }
    float m  = s * (1.f / 256.f);
    float var = q * (1.f / 256.f) - m * m;
    float rstd = rsqrtf(var + 1e-5f);
    float4 w0 = *(const float4*)(w + c0), w1 = *(const float4*)(w + c1);
    float4 b0 = *(const float4*)(bb + c0), b1 = *(const float4*)(bb + c1);
    float4 o0, o1;
    o0.x = (v0.x - m) * rstd * w0.x + b0.x;
    o0.y = (v0.y - m) * rstd * w0.y + b0.y;
    o0.z = (v0.z - m) * rstd * w0.z + b0.z;
    o0.w = (v0.w - m) * rstd * w0.w + b0.w;
    o1.x = (v1.x - m) * rstd * w1.x + b1.x;
    o1.y = (v1.y - m) * rstd * w1.y + b1.y;
    o1.z = (v1.z - m) * rstd * w1.z + b1.z;
    o1.w = (v1.w - m) * rstd * w1.w + b1.w;
    sth4(op + c0, o0);
    sth4(op + c1, o1);
}

// ---------------------------------------------------------------------------
// tc_in (inproj): xz = hn(8192,256) * W(1024,256)^T; hn fp16.
// Transpose epilogue to fp16: feat<512 -> xt raw; >=512 -> zt silu'd.
// ---------------------------------------------------------------------------
#define NT_ASZ (128 * 36)
#define NT_BSZ (64 * 36)
#define NT_SMEM ((2 * NT_ASZ + 2 * NT_BSZ) * 4)

__global__ __launch_bounds__(256)
void tc_in(const __half* __restrict__ A, const float* __restrict__ B,
           __half* __restrict__ xt, __half* __restrict__ zt) {
    const int K = DM;
    extern __shared__ uint32_t sm_nt[];
    uint32_t* As = sm_nt;
    uint32_t* Bs = sm_nt + 2 * NT_ASZ;
    int tid = threadIdx.x, lane = tid & 31, wid = tid >> 5;
    int m0 = blockIdx.y * 128, n0 = blockIdx.x * 64;
    int wm = (wid >> 1) * 32, wn = (wid & 1) * 32;
    int gr = lane >> 2, gc = lane & 3;
    float acc[2][4][4];
#pragma unroll
    for (int i = 0; i < 2; i++)
#pragma unroll
        for (int j = 0; j < 4; j++)
#pragma unroll
            for (int q = 0; q < 4; q++) acc[i][j][q] = 0.f;
    int la_m = tid >> 3, la_k = (tid & 7) * 4;
    int lb_n = tid >> 2, lb_k = (tid & 3) * 8;
    const __half* Apt = A + (size_t)(m0 + la_m) * K + la_k;
    const float* Bpt = B + (size_t)(n0 + lb_n) * K + lb_k;
    float4 ar[4], br[2];
#pragma unroll
    for (int i = 0; i < 4; i++) ar[i] = ldh4(Apt + (size_t)(i * 32) * K);
    br[0] = *(const float4*)(Bpt);
    br[1] = *(const float4*)(Bpt + 4);
    int buf = 0;
#pragma unroll
    for (int i = 0; i < 4; i++)
        *(uint4*)&As[(la_m + i * 32) * 36 + la_k] = cvt4(ar[i]);
    *(uint4*)&Bs[lb_n * 36 + lb_k]     = cvt4(br[0]);
    *(uint4*)&Bs[lb_n * 36 + lb_k + 4] = cvt4(br[1]);
    __syncthreads();

    for (int k0 = 32; k0 <= K; k0 += 32) {
        if (k0 < K) {
#pragma unroll
            for (int i = 0; i < 4; i++)
                ar[i] = ldh4(Apt + (size_t)(i * 32) * K + k0);
            br[0] = *(const float4*)(Bpt + k0);
            br[1] = *(const float4*)(Bpt + k0 + 4);
        }
        const uint32_t* Ab = As + buf * NT_ASZ;
        const uint32_t* Bb = Bs + buf * NT_BSZ;
#pragma unroll
        for (int ks = 0; ks < 4; ks++) {
            int kb = ks * 8;
            uint32_t a[2][4];
#pragma unroll
            for (int mi = 0; mi < 2; mi++) {
                int rb = wm + mi * 16 + gr;
                a[mi][0] = Ab[rb * 36 + kb + gc];
                a[mi][1] = Ab[(rb + 8) * 36 + kb + gc];
                a[mi][2] = Ab[rb * 36 + kb + gc + 4];
                a[mi][3] = Ab[(rb + 8) * 36 + kb + gc + 4];
            }
#pragma unroll
            for (int ni = 0; ni < 4; ni++) {
                uint32_t b0 = Bb[(wn + ni * 8 + gr) * 36 + kb + gc];
                uint32_t b1 = Bb[(wn + ni * 8 + gr) * 36 + kb + gc + 4];
#pragma unroll
                for (int mi = 0; mi < 2; mi++)
                    mma_tf32(acc[mi][ni], a[mi], b0, b1);
            }
        }
        if (k0 < K) {
            int nb2 = buf ^ 1;
#pragma unroll
            for (int i = 0; i < 4; i++)
                *(uint4*)&As[nb2 * NT_ASZ + (la_m + i * 32) * 36 + la_k] = cvt4(ar[i]);
            *(uint4*)&Bs[nb2 * NT_BSZ + lb_n * 36 + lb_k]     = cvt4(br[0]);
            *(uint4*)&Bs[nb2 * NT_BSZ + lb_n * 36 + lb_k + 4] = cvt4(br[1]);
            __syncthreads();
            buf = nb2;
        }
    }
    // transpose epilogue via smem: st[feat][tok], stride 132
    float* st = (float*)sm_nt;
    __syncthreads();
#pragma unroll
    for (int mi = 0; mi < 2; mi++) {
        int r0 = wm + mi * 16 + gr;
#pragma unroll
        for (int ni = 0; ni < 4; ni++) {
            int cc = wn + ni * 8 + 2 * gc;
            st[cc * 132 + r0]           = acc[mi][ni][0];
            st[(cc + 1) * 132 + r0]     = acc[mi][ni][1];
            st[cc * 132 + r0 + 8]       = acc[mi][ni][2];
            st[(cc + 1) * 132 + r0 + 8] = acc[mi][ni][3];
        }
    }
    __syncthreads();
    int b = m0 / NS, s0 = m0 % NS;
#pragma unroll
    for (int rr = wid; rr < 64; rr += 8) {
        int f = n0 + rr;
        float4 v = *(float4*)&st[rr * 132 + lane * 4];
        if (f < DI) {
            sth4(xt + ((size_t)b * DI + f) * NS + s0 + lane * 4, v);
        } else {
            v.x = silu_f(v.x); v.y = silu_f(v.y);
            v.z = silu_f(v.z); v.w = silu_f(v.w);
            sth4(zt + ((size_t)b * DI + f - DI) * NS + s0 + lane * 4, v);
        }
    }
}

// ---------------------------------------------------------------------------
// conv_t: causal 4-tap depthwise conv + SiLU, fp16 in/out, streaming.
// ---------------------------------------------------------------------------
__global__ __launch_bounds__(256)
void conv_t(const __half* __restrict__ xt, const float* __restrict__ cw,
            const float* __restrict__ cb, __half* __restrict__ xc) {
    int d = blockIdx.x, b = blockIdx.y;
    const __half* row = xt + ((size_t)b * DI + d) * NS;
    __half* orow = xc + ((size_t)b * DI + d) * NS;
    float w0 = cw[d * 4 + 0], w1 = cw[d * 4 + 1];
    float w2 = cw[d * 4 + 2], w3 = cw[d * 4 + 3];
    float bias = cb[d];
    int s = threadIdx.x * 8;
    float in[12];
    float4 A = (s == 0) ? make_float4(0.f, 0.f, 0.f, 0.f) : ldh4(row + s - 4);
    float4 Bv = ldh4(row + s);
    float4 Cv = ldh4(row + s + 4);
    in[0] = A.x; in[1] = A.y; in[2] = A.z; in[3] = A.w;
    in[4] = Bv.x; in[5] = Bv.y; in[6] = Bv.z; in[7] = Bv.w;
    in[8] = Cv.x; in[9] = Cv.y; in[10] = Cv.z; in[11] = Cv.w;
    float o[8];
#pragma unroll
    for (int k = 0; k < 8; k++) {
        float a = bias + w0 * in[k + 1] + w1 * in[k + 2]
                       + w2 * in[k + 3] + w3 * in[k + 4];
        o[k] = silu_f(a);
    }
    sth4(orow + s,     make_float4(o[0], o[1], o[2], o[3]));
    sth4(orow + s + 4, make_float4(o[4], o[5], o[6], o[7]));
}

// ---------------------------------------------------------------------------
// tc_xp (xproj): per batch, dblt(48, s) = xpW(48,512) x xc(d,s); K=512.
// s-tile 32 -> 256 blocks. 8 warps as 2(m)x4(n), warp tile 32(m)x8(s).
// ---------------------------------------------------------------------------
#define XP_ASZ (64 * 36)
#define XP_BSZ (32 * 40)
#define XP_SMEM ((2 * XP_ASZ + 2 * XP_BSZ) * 4)

__global__ __launch_bounds__(256)
void tc_xp(const float* __restrict__ W, const __half* __restrict__ X,
           float* __restrict__ Dt) {
    extern __shared__ uint32_t sm_xp[];
    uint32_t* As = sm_xp;
    uint32_t* Bs = sm_xp + 2 * XP_ASZ;
    int b = blockIdx.z;
    int s0 = blockIdx.x * 32;
    const __half* Xb = X + (size_t)b * DI * NS;
    float* Db = Dt + (size_t)b * 48 * NS;
    int tid = threadIdx.x, lane = tid & 31, wid = tid >> 5;
    int wm = (wid >> 2) * 32, wn = (wid & 3) * 8;
    int gr = lane >> 2, gc = lane & 3;
    float acc[2][4];
#pragma unroll
    for (int i = 0; i < 2; i++)
#pragma unroll
        for (int q = 0; q < 4; q++) acc[i][q] = 0.f;
    int la_m = tid >> 2, la_k = (tid & 3) * 8;
    int bk = tid >> 3, bn4 = (tid & 7) * 4;
    bool avalid = (la_m < 48);
    const float* Apt = W + (size_t)la_m * DI + la_k;
    float4 zero = make_float4(0.f, 0.f, 0.f, 0.f);
    float4 ar[2], br;
    ar[0] = avalid ? *(const float4*)(Apt)     : zero;
    ar[1] = avalid ? *(const float4*)(Apt + 4) : zero;
    br = ldh4(Xb + (size_t)bk * NS + s0 + bn4);
    int buf = 0;
    *(uint4*)&As[la_m * 36 + la_k]     = cvt4(ar[0]);
    *(uint4*)&As[la_m * 36 + la_k + 4] = cvt4(ar[1]);
    *(uint4*)&Bs[bk * 40 + bn4] = cvt4(br);
    __syncthreads();

    for (int k0 = 32; k0 <= DI; k0 += 32) {
        if (k0 < DI) {
            ar[0] = avalid ? *(const float4*)(Apt + k0)     : zero;
            ar[1] = avalid ? *(const float4*)(Apt + k0 + 4) : zero;
            br = ldh4(Xb + (size_t)(k0 + bk) * NS + s0 + bn4);
        }
        const uint32_t* Ab = As + buf * XP_ASZ;
        const uint32_t* Bb = Bs + buf * XP_BSZ;
#pragma unroll
        for (int ks = 0; ks < 4; ks++) {
            int kb = ks * 8;
            uint32_t a[2][4];
#pragma unroll
            for (int mi = 0; mi < 2; mi++) {
                int rb = wm + mi * 16 + gr;
                a[mi][0] = Ab[rb * 36 + kb + gc];
                a[mi][1] = Ab[(rb + 8) * 36 + kb + gc];
                a[mi][2] = Ab[rb * 36 + kb + gc + 4];
                a[mi][3] = Ab[(rb + 8) * 36 + kb + gc + 4];
            }
            int nn = wn + gr;
            uint32_t b0 = Bb[(kb + gc) * 40 + nn];
            uint32_t b1 = Bb[(kb + gc + 4) * 40 + nn];
#pragma unroll
            for (int mi = 0; mi < 2; mi++)
                mma_tf32(acc[mi], a[mi], b0, b1);
        }
        if (k0 < DI) {
            int nb2 = buf ^ 1;
            *(uint4*)&As[nb2 * XP_ASZ + la_m * 36 + la_k]     = cvt4(ar[0]);
            *(uint4*)&As[nb2 * XP_ASZ + la_m * 36 + la_k + 4] = cvt4(ar[1]);
            *(uint4*)&Bs[nb2 * XP_BSZ + bk * 40 + bn4] = cvt4(br);
            __syncthreads();
            buf = nb2;
        }
    }
#pragma unroll
    for (int mi = 0; mi < 2; mi++) {
        int m = wm + mi * 16 + gr;
        int sc = s0 + wn + 2 * gc;
        if (m < 48)
            *(float2*)(Db + (size_t)m * NS + sc) =
                make_float2(acc[mi][0], acc[mi][1]);
        if (m + 8 < 48)
            *(float2*)(Db + (size_t)(m + 8) * NS + sc) =
                make_float2(acc[mi][2], acc[mi][3]);
    }
}

// ---------------------------------------------------------------------------
// scan: fused dtproj + chunked smem staging, SOFTWARE-PIPELINED:
// next chunk's GMEM loads issue right after the first barrier, overlapping
// dt-compute + recurrence. 3 barriers/chunk. 128 threads = 8 channels.
// ---------------------------------------------------------------------------
#define SCH 64

__global__ __launch_bounds__(128)
void scan_kernel(const __half* __restrict__ xcp, const __half* __restrict__ ztp,
                 const float* __restrict__ dblt,
                 const float* __restrict__ dtW, const float* __restrict__ dtb,
                 const float* __restrict__ Alog, const float* __restrict__ Dp,
                 __half* __restrict__ yout) {
    __shared__ float sdp[16][SCH];
    __shared__ float sB [16][SCH + 4];
    __shared__ float sC [16][SCH + 4];
    __shared__ float sdt[8][SCH + 4];
    __shared__ float sx [8][SCH + 4];
    __shared__ float sz [8][SCH + 4];
    __shared__ float sy [8][SCH + 4];
    __shared__ float sW [8][16];
    __shared__ float sbias[8];

    int b = blockIdx.y;
    int d0 = blockIdx.x * 8;
    int tid = threadIdx.x, lane = tid & 31, warp = tid >> 5;
    int dl = lane >> 4, n = lane & 15;
    int dloc = warp * 2 + dl;
    int d = d0 + dloc;

    {
        int dd = tid >> 4, j = tid & 15;
        sW[dd][j] = dtW[(size_t)(d0 + dd) * 16 + j];
    }
    if (tid < 8) sbias[tid] = dtb[d0 + tid];

    float a  = -__expf(Alog[d * DSTATE + n]);
    float Dv = Dp[d];
    float hst = 0.f;
    const float* dpb = dblt + (size_t)b * 48 * NS;

    // staging maps
    int r16 = tid >> 3, c16 = (tid & 7) * 8;    // dp/B/C: row 0..15, two f4
    int r8  = tid >> 4, c8  = (tid & 15) * 4;   // x/z/y: row 0..7, one f4
    const float* dpr = dpb + (size_t)r16 * NS + c16;
    const float* dBr = dpb + (size_t)(16 + r16) * NS + c16;
    const float* dCr = dpb + (size_t)(32 + r16) * NS + c16;
    const __half* xr = xcp + ((size_t)b * DI + d0 + r8) * NS + c8;
    const __half* zr = ztp + ((size_t)b * DI + d0 + r8) * NS + c8;
    __half* yw = yout + ((size_t)b * DI + d0 + r8) * NS + c8;

    // prologue: load chunk 0 into registers
    float4 rdp0 = *(const float4*)(dpr);
    float4 rdp1 = *(const float4*)(dpr + 4);
    float4 rB0  = *(const float4*)(dBr);
    float4 rB1  = *(const float4*)(dBr + 4);
    float4 rC0  = *(const float4*)(dCr);
    float4 rC1  = *(const float4*)(dCr + 4);
    float4 rx   = ldh4(xr);
    float4 rz   = ldh4(zr);

    for (int t0 = 0; t0 < NS; t0 += SCH) {
        // commit registers for chunk t0 to smem
        *(float4*)&sdp[r16][c16]     = rdp0;
        *(float4*)&sdp[r16][c16 + 4] = rdp1;
        *(float4*)&sB[r16][c16]      = rB0;
        *(float4*)&sB[r16][c16 + 4]  = rB1;
        *(float4*)&sC[r16][c16]      = rC0;
        *(float4*)&sC[r16][c16 + 4]  = rC1;
        *(float4*)&sx[r8][c8]        = rx;
        *(float4*)&sz[r8][c8]        = rz;
        __syncthreads();
        // prefetch chunk t0+SCH (latency overlaps dt + recurrence below)
        int tn = t0 + SCH;
        if (tn < NS) {
            rdp0 = *(const float4*)(dpr + tn);
            rdp1 = *(const float4*)(dpr + tn + 4);
            rB0  = *(const float4*)(dBr + tn);
            rB1  = *(const float4*)(dBr + tn + 4);
            rC0  = *(const float4*)(dCr + tn);
            rC1  = *(const float4*)(dCr + tn + 4);
            rx   = ldh4(xr + tn);
            rz   = ldh4(zr + tn);
        }
        // dt = softplus(W @ dtpre + b)
        {
            int dd = tid >> 4, tt = (tid & 15) * 4;
            float bi = sbias[dd];
            float a0 = bi, a1 = bi, a2 = bi, a3 = bi;
#pragma unroll
            for (int j = 0; j < 16; j++) {
                float w = sW[dd][j];
                a0 = fmaf(w, sdp[j][tt],     a0);
                a1 = fmaf(w, sdp[j][tt + 1], a1);
                a2 = fmaf(w, sdp[j][tt + 2], a2);
                a3 = fmaf(w, sdp[j][tt + 3], a3);
            }
            sdt[dd][tt]     = softplus_f(a0);
            sdt[dd][tt + 1] = softplus_f(a1);
            sdt[dd][tt + 2] = softplus_f(a2);
            sdt[dd][tt + 3] = softplus_f(a3);
        }
        __syncthreads();
        // recurrence over chunk
        for (int g = 0; g < SCH; g += 4) {
            float4 dt4 = *(const float4*)&sdt[dloc][g];
            float4 x4  = *(const float4*)&sx[dloc][g];
            float4 z4  = *(const float4*)&sz[dloc][g];
            float4 B4  = *(const float4*)&sB[n][g];
            float4 C4  = *(const float4*)&sC[n][g];
            float yo[4];
#pragma unroll
            for (int j = 0; j < 4; j++) {
                float dtv = (&dt4.x)[j], xv = (&x4.x)[j], zv = (&z4.x)[j];
                float Bv = (&B4.x)[j], Cv = (&C4.x)[j];
                float dA = __expf(dtv * a);
                hst = fmaf(dA, hst, dtv * xv * Bv);
                float p = hst * Cv;
                p += __shfl_xor_sync(0xffffffffu, p, 1);
                p += __shfl_xor_sync(0xffffffffu, p, 2);
                p += __shfl_xor_sync(0xffffffffu, p, 4);
                p += __shfl_xor_sync(0xffffffffu, p, 8);
                yo[j] = fmaf(Dv, xv, p) * zv;
            }
            if (n == 0)
                *(float4*)&sy[dloc][g] = make_float4(yo[0], yo[1], yo[2], yo[3]);
        }
        __syncthreads();
        // y chunk out (coalesced); next iteration's STS hits disjoint arrays
        sth4(yw + t0, *(float4*)&sy[r8][c8]);
    }
}

// ---------------------------------------------------------------------------
// tc_op (outproj): per batch, h(s,dm) = W(256,512) x y(d,s); y fp16.
// ---------------------------------------------------------------------------
#define OP_ASZ (128 * 36)
#define OP_BSZ (32 * 72)
#define OP_SMEM ((2 * OP_ASZ + 2 * OP_BSZ) * 4)

__global__ __launch_bounds__(256)
void tc_op(const float* __restrict__ W, const __half* __restrict__ Y,
           float* __restrict__ H) {
    extern __shared__ uint32_t sm_op[];
    uint32_t* As = sm_op;
    uint32_t* Bs = sm_op + 2 * OP_ASZ;
    int b = blockIdx.z;
    int m0 = blockIdx.y * 128, s0 = blockIdx.x * 64;
    const __half* Yb = Y + (size_t)b * DI * NS;
    int tid = threadIdx.x, lane = tid & 31, wid = tid >> 5;
    int wm = (wid >> 1) * 32, wn = (wid & 1) * 32;
    int gr = lane >> 2, gc = lane & 3;
    float acc[2][4][4];
#pragma unroll
    for (int i = 0; i < 2; i++)
#pragma unroll
        for (int j = 0; j < 4; j++)
#pragma unroll
            for (int q = 0; q < 4; q++) acc[i][j][q] = 0.f;
    int la_m = tid >> 3, la_k = (tid & 7) * 4;
    int bk = tid >> 4, bn4 = (tid & 15) * 4;
    const float* Apt = W + (size_t)(m0 + la_m) * DI + la_k;
    float4 ar[4], br[2];
#pragma unroll
    for (int i = 0; i < 4; i++) ar[i] = *(const float4*)(Apt + (size_t)(i * 32) * DI);
#pragma unroll
    for (int i = 0; i < 2; i++)
        br[i] = ldh4(Yb + (size_t)(bk + i * 16) * NS + s0 + bn4);
    int buf = 0;
#pragma unroll
    for (int i = 0; i < 4; i++)
        *(uint4*)&As[(la_m + i * 32) * 36 + la_k] = cvt4(ar[i]);
#pragma unroll
    for (int i = 0; i < 2; i++)
        *(uint4*)&Bs[(bk + i * 16) * 72 + bn4] = cvt4(br[i]);
    __syncthreads();

    for (int k0 = 32; k0 <= DI; k0 += 32) {
        if (k0 < DI) {
#pragma unroll
            for (int i = 0; i < 4; i++)
                ar[i] = *(const float4*)(Apt + (size_t)(i * 32) * DI + k0);
#pragma unroll
            for (int i = 0; i < 2; i++)
                br[i] = ldh4(Yb + (size_t)(k0 + bk + i * 16) * NS + s0 + bn4);
        }
        const uint32_t* Ab = As + buf * OP_ASZ;
        const uint32_t* Bb = Bs + buf * OP_BSZ;
#pragma unroll
        for (int ks = 0; ks < 4; ks++) {
            int kb = ks * 8;
            uint32_t a[2][4];
#pragma unroll
            for (int mi = 0; mi < 2; mi++) {
                int rb = wm + mi * 16 + gr;
                a[mi][0] = Ab[rb * 36 + kb + gc];
                a[mi][1] = Ab[(rb + 8) * 36 + kb + gc];
                a[mi][2] = Ab[rb * 36 + kb + gc + 4];
                a[mi][3] = Ab[(rb + 8) * 36 + kb + gc + 4];
            }
#pragma unroll
            for (int ni = 0; ni < 4; ni++) {
                int nn = wn + ni * 8 + gr;
                uint32_t b0 = Bb[(kb + gc) * 72 + nn];
                uint32_t b1 = Bb[(kb + gc + 4) * 72 + nn];
#pragma unroll
                for (int mi = 0; mi < 2; mi++)
                    mma_tf32(acc[mi][ni], a[mi], b0, b1);
            }
        }
        if (k0 < DI) {
            int nb2 = buf ^ 1;
#pragma unroll
            for (int i = 0; i < 4; i++)
                *(uint4*)&As[nb2 * OP_ASZ + (la_m + i * 32) * 36 + la_k] = cvt4(ar[i]);
#pragma unroll
            for (int i = 0; i < 2; i++)
                *(uint4*)&Bs[nb2 * OP_BSZ + (bk + i * 16) * 72 + bn4] = cvt4(br[i]);
            __syncthreads();
            buf = nb2;
        }
    }
#pragma unroll
    for (int mi = 0; mi < 2; mi++) {
        int dm = m0 + wm + mi * 16 + gr;
#pragma unroll
        for (int ni = 0; ni < 4; ni++) {
            int s = s0 + wn + ni * 8 + 2 * gc;
            size_t r0 = (size_t)(b * NS + s) * DM;
            size_t r1 = (size_t)(b * NS + s + 1) * DM;
            H[r0 + dm]     = acc[mi][ni][0];
            H[r1 + dm]     = acc[mi][ni][1];
            H[r0 + dm + 8] = acc[mi][ni][2];
            H[r1 + dm + 8] = acc[mi][ni][3];
        }
    }
}

// ---------------------------------------------------------------------------
// head
// ---------------------------------------------------------------------------
__global__ __launch_bounds__(256)
void head_kernel(const float* __restrict__ hin, const float* __restrict__ w,
                 float* __restrict__ out) {
    int wid = threadIdx.x >> 5, lane = threadIdx.x & 31;
    int row = blockIdx.x * 8 + wid;
    const float* hp = hin + (size_t)row * DM;
    int c0 = lane * 4, c1 = 128 + lane * 4;
    float4 v0 = *(const float4*)(hp + c0);
    float4 v1 = *(const float4*)(hp + c1);
    float4 w0 = *(const float4*)(w + c0);
    float4 w1 = *(const float4*)(w + c1);
    float s = v0.x*w0.x + v0.y*w0.y + v0.z*w0.z + v0.w*w0.w +
              v1.x*w1.x + v1.y*w1.y + v1.z*w1.z + v1.w*w1.w;
#pragma unroll
    for (int o = 16; o > 0; o >>= 1) s += __shfl_xor_sync(0xffffffffu, s, o);
    if (lane == 0) out[row] = s;
}

// ---------------------------------------------------------------------------
// host
// ---------------------------------------------------------------------------
extern "C" void kernel_launch(void* const* d_in, const int* in_sizes, int n_in,
                              void* d_out, int out_size) {
    const float* x_src     = (const float*)d_in[0];
    const float* in_W      = (const float*)d_in[2];
    const float* norm_w    = (const float*)d_in[3];
    const float* norm_b    = (const float*)d_in[4];
    const float* inproj_W  = (const float*)d_in[5];
    const float* conv_w    = (const float*)d_in[6];
    const float* conv_b    = (const float*)d_in[7];
    const float* xproj_W   = (const float*)d_in[8];
    const float* dtproj_W  = (const float*)d_in[9];
    const float* dtproj_b  = (const float*)d_in[10];
    const float* A_log     = (const float*)d_in[11];
    const float* D_param   = (const float*)d_in[12];
    const float* outproj_W = (const float*)d_in[13];
    const float* out_W     = (const float*)d_in[14];
    float* out = (float*)d_out;

    static int smem_set = 0;
    if (!smem_set) {
        cudaFuncSetAttribute(tc_in, cudaFuncAttributeMaxDynamicSharedMemorySize,
                             NT_SMEM);
        cudaFuncSetAttribute(tc_op, cudaFuncAttributeMaxDynamicSharedMemorySize,
                             OP_SMEM);
        cudaFuncSetAttribute(tc_xp, cudaFuncAttributeMaxDynamicSharedMemorySize,
                             XP_SMEM);
        smem_set = 1;
    }

    float *ph, *pres, *pdblt;
    __half *phn, *pxt, *pzt, *pxc, *py;
    cudaGetSymbolAddress((void**)&ph,    g_h);
    cudaGetSymbolAddress((void**)&pres,  g_res);
    cudaGetSymbolAddress((void**)&phn,   g_hn);
    cudaGetSymbolAddress((void**)&pxt,   g_xt);
    cudaGetSymbolAddress((void**)&pzt,   g_zt);
    cudaGetSymbolAddress((void**)&pxc,   g_xc);
    cudaGetSymbolAddress((void**)&pdblt, g_dblt);
    cudaGetSymbolAddress((void**)&py,    g_y);

    embed_kernel<<<NTOK, 256>>>(x_src, in_W, ph);

    for (int l = 0; l < 4; l++) {
        ln_kernel<<<NTOK / 8, 256>>>(ph, pres, phn,
                                     norm_w + l * DM, norm_b + l * DM,
                                     (l == 0) ? 1 : 0);
        tc_in<<<dim3(1024 / 64, NTOK / 128), 256, NT_SMEM>>>(
            phn, inproj_W + (size_t)l * 1024 * DM, pxt, pzt);
        conv_t<<<dim3(DI, NB), 256>>>(
            pxt, conv_w + (size_t)l * DI * 4, conv_b + (size_t)l * DI, pxc);
        tc_xp<<<dim3(NS / 32, 1, NB), 256, XP_SMEM>>>(
            xproj_W + (size_t)l * 48 * DI, pxc, pdblt);
        scan_kernel<<<dim3(DI / 8, NB), 128>>>(
            pxc, pzt, pdblt,
            dtproj_W + (size_t)l * DI * 16, dtproj_b + (size_t)l * DI,
            A_log + (size_t)l * DI * DSTATE, D_param + (size_t)l * DI, py);
        tc_op<<<dim3(NS / 64, DM / 128, NB), 256, OP_SMEM>>>(
            outproj_W + (size_t)l * DM * DI, py, ph);
    }

    head_kernel<<<NTOK / 8, 256>>>(ph, out_W, out);
}